// round 1
// baseline (speedup 1.0000x reference)
#include <cuda_runtime.h>
#include <cstdint>

// ---------------------------------------------------------------------------
// PIGNN forward, fp32 baseline.
// Pipeline:
//   tmpn = relu(x @ enc_n_W1 + b1)            (mlp1, K=9)
//   h    = tmpn @ enc_n_W2 + b2               (gemm128 PLAIN/STORE)
//   tmpe = relu(edge_attr @ enc_e_W1 + b1)    (mlp1, K=10)
//   e    = tmpe @ enc_e_W2 + b2               (gemm128 PLAIN/STORE)
//   6x:
//     agg = 0
//     msg = relu([h[src]|h[dst]|e] @ mW + mb) scatter-RED into agg[dst]
//     h  += relu([h|agg] @ uW + ub)
//   f1   = relu(h @ dec_W1 + b1)              (gemm128 PLAIN/STORE relu)
//   out  = mask( relu(f1@W2+b2) @ W3 + b3 )   (dec2 fused)
// ---------------------------------------------------------------------------

#define NN_MAX 100000
#define NE_MAX 600000

// scratch (allocation-free: __device__ globals)
__device__ float g_h   [(size_t)NN_MAX * 128];
__device__ float g_agg [(size_t)NN_MAX * 128];
__device__ float g_tmpn[(size_t)NN_MAX * 128];
__device__ float g_e   [(size_t)NE_MAX * 128];
__device__ float g_tmpe[(size_t)NE_MAX * 128];

// ---------------------------------------------------------------------------
// zero fill
__global__ void zero_kernel(float* __restrict__ p, int n4) {
    int i = blockIdx.x * blockDim.x + threadIdx.x;
    if (i < n4) reinterpret_cast<float4*>(p)[i] = make_float4(0.f, 0.f, 0.f, 0.f);
}

// ---------------------------------------------------------------------------
// tiny-K first linear + relu:  out[row][col] = relu(b[col] + sum_k X[row][k]*W[k][col])
// one block (128 threads) per row; X row broadcast, W coalesced (L2-hot).
__global__ void mlp1_kernel(const float* __restrict__ X, const float* __restrict__ W,
                            const float* __restrict__ b, float* __restrict__ out, int K) {
    int row = blockIdx.x;
    int col = threadIdx.x;
    float acc = b[col];
    const float* xr = X + (size_t)row * K;
    for (int k = 0; k < K; ++k)
        acc += xr[k] * W[k * 128 + col];
    out[(size_t)row * 128 + col] = fmaxf(acc, 0.f);
}

// ---------------------------------------------------------------------------
// vectorized no-return global reduction
__device__ __forceinline__ void red_add_v4(float* addr, float a, float b, float c, float d) {
    asm volatile("red.global.add.v4.f32 [%0], {%1,%2,%3,%4};"
                 :: "l"(addr), "f"(a), "f"(b), "f"(c), "f"(d) : "memory");
}

// ---------------------------------------------------------------------------
// Fused tiled GEMM: C = epi( act( A @ W + bias ) )
// BM=128 rows, BN=128 cols (=H), BK=16, 256 threads, 8x8 register tile.
// MODE: 0 plain A (MxK, ld=K) | 1 msg gather [h[src]|h[dst]|e] (K=384) | 2 upd [h|agg] (K=256)
// EPI : 0 store | 1 scatter-RED into Cout[dst[m]] | 2 residual Cout[m] += v
#define GBM 128
#define GBK 16

template<int MODE>
__device__ __forceinline__ void load_tile_regs(
    const float* __restrict__ A, const float* __restrict__ W,
    const int* __restrict__ src, const int* __restrict__ dst,
    const float* __restrict__ H, const float* __restrict__ E_,
    int m0, int M, int K, int kbase, int t,
    float4 wv[2], float4 av[2])
{
#pragma unroll
    for (int r = 0; r < 2; ++r) {
        int id = t + r * 256;
        int kk = id >> 5;
        int c4 = (id & 31) * 4;
        wv[r] = *reinterpret_cast<const float4*>(&W[(size_t)(kbase + kk) * 128 + c4]);
    }
#pragma unroll
    for (int r = 0; r < 2; ++r) {
        int id  = t + r * 256;
        int row = id >> 2;
        int kq  = (id & 3) * 4;
        int m   = m0 + row;
        int mc  = m < M ? m : M - 1;
        int k   = kbase + kq;
        const float* base;
        if (MODE == 0) {
            base = &A[(size_t)mc * K + k];
        } else if (MODE == 1) {
            int seg = k >> 7, kl = k & 127;
            if (seg == 0)      base = &H[(size_t)__ldg(&src[mc]) * 128 + kl];
            else if (seg == 1) base = &H[(size_t)__ldg(&dst[mc]) * 128 + kl];
            else               base = &E_[(size_t)mc * 128 + kl];
        } else {
            if (k < 128) base = &H [(size_t)mc * 128 + k];
            else         base = &E_[(size_t)mc * 128 + (k - 128)];
        }
        av[r] = *reinterpret_cast<const float4*>(base);
    }
}

template<int MODE, int EPI, bool RELU>
__global__ __launch_bounds__(256)
void gemm128(const float* __restrict__ A, const float* __restrict__ W,
             const float* __restrict__ bias, float* __restrict__ Cout,
             const int* __restrict__ src, const int* __restrict__ dst,
             const float* __restrict__ H, const float* __restrict__ E_,
             int M, int K)
{
    __shared__ float As[GBK][GBM + 4];   // transposed A tile (132-float rows keep 16B align)
    __shared__ float Ws[GBK][128];

    const int t  = threadIdx.x;
    const int tx = t & 15;     // col group: cols tx*8 .. tx*8+7
    const int ty = t >> 4;     // row group: rows ty*8 .. ty*8+7
    const int m0 = blockIdx.x * GBM;
    const int nchunks = K / GBK;

    float acc[8][8];
#pragma unroll
    for (int i = 0; i < 8; ++i)
#pragma unroll
        for (int j = 0; j < 8; ++j) acc[i][j] = 0.f;

    float4 wv[2], av[2];
    load_tile_regs<MODE>(A, W, src, dst, H, E_, m0, M, K, 0, t, wv, av);

    for (int ch = 0; ch < nchunks; ++ch) {
        // commit prefetched tile to smem
#pragma unroll
        for (int r = 0; r < 2; ++r) {
            int id = t + r * 256;
            int kk = id >> 5;
            int c4 = (id & 31) * 4;
            *reinterpret_cast<float4*>(&Ws[kk][c4]) = wv[r];
            int row = id >> 2;
            int kq  = (id & 3) * 4;
            As[kq + 0][row] = av[r].x;
            As[kq + 1][row] = av[r].y;
            As[kq + 2][row] = av[r].z;
            As[kq + 3][row] = av[r].w;
        }
        __syncthreads();
        if (ch + 1 < nchunks)
            load_tile_regs<MODE>(A, W, src, dst, H, E_, m0, M, K, (ch + 1) * GBK, t, wv, av);

#pragma unroll
        for (int k = 0; k < GBK; ++k) {
            float4 a0 = *reinterpret_cast<const float4*>(&As[k][ty * 8]);
            float4 a1 = *reinterpret_cast<const float4*>(&As[k][ty * 8 + 4]);
            float4 b0 = *reinterpret_cast<const float4*>(&Ws[k][tx * 8]);
            float4 b1 = *reinterpret_cast<const float4*>(&Ws[k][tx * 8 + 4]);
            float a[8] = {a0.x, a0.y, a0.z, a0.w, a1.x, a1.y, a1.z, a1.w};
            float b[8] = {b0.x, b0.y, b0.z, b0.w, b1.x, b1.y, b1.z, b1.w};
#pragma unroll
            for (int i = 0; i < 8; ++i)
#pragma unroll
                for (int j = 0; j < 8; ++j)
                    acc[i][j] += a[i] * b[j];
        }
        __syncthreads();
    }

    // epilogue
#pragma unroll
    for (int i = 0; i < 8; ++i) {
        int m = m0 + ty * 8 + i;
        if (m >= M) continue;
        float v[8];
#pragma unroll
        for (int j = 0; j < 8; ++j) {
            float x = acc[i][j] + bias[tx * 8 + j];
            v[j] = RELU ? fmaxf(x, 0.f) : x;
        }
        if (EPI == 0) {
            float* cp = &Cout[(size_t)m * 128 + tx * 8];
            *reinterpret_cast<float4*>(cp)     = make_float4(v[0], v[1], v[2], v[3]);
            *reinterpret_cast<float4*>(cp + 4) = make_float4(v[4], v[5], v[6], v[7]);
        } else if (EPI == 1) {
            float* base = &Cout[(size_t)__ldg(&dst[m]) * 128 + tx * 8];
            red_add_v4(base,     v[0], v[1], v[2], v[3]);
            red_add_v4(base + 4, v[4], v[5], v[6], v[7]);
        } else {
            float* cp = &Cout[(size_t)m * 128 + tx * 8];
            float4 o0 = *reinterpret_cast<const float4*>(cp);
            float4 o1 = *reinterpret_cast<const float4*>(cp + 4);
            o0.x += v[0]; o0.y += v[1]; o0.z += v[2]; o0.w += v[3];
            o1.x += v[4]; o1.y += v[5]; o1.z += v[6]; o1.w += v[7];
            *reinterpret_cast<float4*>(cp)     = o0;
            *reinterpret_cast<float4*>(cp + 4) = o1;
        }
    }
}

// ---------------------------------------------------------------------------
// fused decoder tail: f2 = relu(f1@W2+b2) (64), pred = f2@W3+b3 (15), masked.
__global__ void dec2_kernel(const float* __restrict__ f1, const float* __restrict__ W2,
                            const float* __restrict__ b2, const float* __restrict__ W3,
                            const float* __restrict__ b3, const float* __restrict__ bc_disp,
                            const float* __restrict__ bc_rot, const float* __restrict__ face_mask,
                            float* __restrict__ out, int N)
{
    __shared__ float W2s[128 * 64];
    __shared__ float W3s[64 * 15];
    __shared__ float b2s[64], b3s[16];
    __shared__ float f1s[2][128];
    __shared__ float f2s[2][64];

    int t = threadIdx.x;  // 128
    for (int i = t; i < 128 * 64; i += 128) W2s[i] = W2[i];
    for (int i = t; i < 64 * 15;  i += 128) W3s[i] = W3[i];
    if (t < 64) b2s[t] = b2[t];
    if (t < 15) b3s[t] = b3[t];
    __syncthreads();

    int base = blockIdx.x * 64;
    for (int it = 0; it < 32; ++it) {
        int n0 = base + it * 2;
#pragma unroll
        for (int r = 0; r < 2; ++r) {
            int n = n0 + r;
            f1s[r][t] = (n < N) ? f1[(size_t)n * 128 + t] : 0.f;
        }
        __syncthreads();
        {
            int rn = t >> 6, j = t & 63;
            float acc = b2s[j];
#pragma unroll 8
            for (int k = 0; k < 128; ++k) acc += f1s[rn][k] * W2s[k * 64 + j];
            f2s[rn][j] = fmaxf(acc, 0.f);
        }
        __syncthreads();
        if (t < 30) {
            int rr = t / 15, c = t % 15;
            int n = n0 + rr;
            if (n < N) {
                float acc = b3s[c];
#pragma unroll 8
                for (int k = 0; k < 64; ++k) acc += f2s[rr][k] * W3s[k * 15 + c];
                float mask;
                if (c < 2)       mask = 1.f - bc_disp[n];
                else if (c == 2) mask = 1.f - bc_rot[n];
                else             mask = face_mask[(size_t)n * 4 + (c - 3) / 3];
                out[(size_t)n * 15 + c] = acc * mask;
            }
        }
        __syncthreads();
    }
}

// ---------------------------------------------------------------------------
extern "C" void kernel_launch(void* const* d_in, const int* in_sizes, int n_in,
                              void* d_out, int out_size)
{
    const float* x         = (const float*)d_in[0];
    const float* edge_attr = (const float*)d_in[1];
    const int*   edge_idx  = (const int*)  d_in[2];
    const float* bc_disp   = (const float*)d_in[3];
    const float* bc_rot    = (const float*)d_in[4];
    const float* face_mask = (const float*)d_in[5];
    const float* enc_n_W1  = (const float*)d_in[6];
    const float* enc_n_b1  = (const float*)d_in[7];
    const float* enc_n_W2  = (const float*)d_in[8];
    const float* enc_n_b2  = (const float*)d_in[9];
    const float* enc_e_W1  = (const float*)d_in[10];
    const float* enc_e_b1  = (const float*)d_in[11];
    const float* enc_e_W2  = (const float*)d_in[12];
    const float* enc_e_b2  = (const float*)d_in[13];
    const float* msg_W     = (const float*)d_in[14];
    const float* msg_b     = (const float*)d_in[15];
    const float* upd_W     = (const float*)d_in[16];
    const float* upd_b     = (const float*)d_in[17];
    const float* dec_W1    = (const float*)d_in[18];
    const float* dec_b1    = (const float*)d_in[19];
    const float* dec_W2    = (const float*)d_in[20];
    const float* dec_b2    = (const float*)d_in[21];
    const float* dec_W3    = (const float*)d_in[22];
    const float* dec_b3    = (const float*)d_in[23];

    const int N = in_sizes[0] / 9;
    const int E = in_sizes[1] / 10;
    const int* src = edge_idx;
    const int* dst = edge_idx + E;

    float *h, *agg, *tmpn, *e, *tmpe;
    cudaGetSymbolAddress((void**)&h,    g_h);
    cudaGetSymbolAddress((void**)&agg,  g_agg);
    cudaGetSymbolAddress((void**)&tmpn, g_tmpn);
    cudaGetSymbolAddress((void**)&e,    g_e);
    cudaGetSymbolAddress((void**)&tmpe, g_tmpe);

    const int gN = (N + 127) / 128;
    const int gE = (E + 127) / 128;

    // encoders
    mlp1_kernel<<<N, 128>>>(x, enc_n_W1, enc_n_b1, tmpn, 9);
    gemm128<0, 0, false><<<gN, 256>>>(tmpn, enc_n_W2, enc_n_b2, h,
                                      nullptr, nullptr, nullptr, nullptr, N, 128);
    mlp1_kernel<<<E, 128>>>(edge_attr, enc_e_W1, enc_e_b1, tmpe, 10);
    gemm128<0, 0, false><<<gE, 256>>>(tmpe, enc_e_W2, enc_e_b2, e,
                                      nullptr, nullptr, nullptr, nullptr, E, 128);

    // message-passing layers
    const int zgrid = (N * 128 / 4 + 255) / 256;
    for (int l = 0; l < 6; ++l) {
        zero_kernel<<<zgrid, 256>>>(agg, N * 128 / 4);
        gemm128<1, 1, true><<<gE, 256>>>(nullptr, msg_W + (size_t)l * 384 * 128,
                                         msg_b + l * 128, agg, src, dst, h, e, E, 384);
        gemm128<2, 2, true><<<gN, 256>>>(nullptr, upd_W + (size_t)l * 256 * 128,
                                         upd_b + l * 128, h, nullptr, nullptr, h, agg, N, 256);
    }

    // decoder
    gemm128<0, 0, true><<<gN, 256>>>(h, dec_W1, dec_b1, tmpn,
                                     nullptr, nullptr, nullptr, nullptr, N, 128);
    dec2_kernel<<<(N + 63) / 64, 128>>>(tmpn, dec_W2, dec_b2, dec_W3, dec_b3,
                                        bc_disp, bc_rot, face_mask, (float*)d_out, N);
}

// round 2
// speedup vs baseline: 1.4191x; 1.4191x over previous
#include <cuda_runtime.h>
#include <cstdint>

// ---------------------------------------------------------------------------
// PIGNN forward, fp32, algebraically restructured.
//
// msg_in @ mW  ==  h[src]@mW1 + h[dst]@mW2 + e@mW3   (mW = [mW1;mW2;mW3])
// so per layer:
//   P1 = h @ mW1                (N x 128, plain GEMM)
//   P2 = h @ mW2                (N x 128, plain GEMM)
//   msg-GEMM: acc = e @ mW3 ; epilogue: relu(acc + b + P1[src] + P2[dst])
//             RED-scatter into agg[dst]                 (E x 128, K=128)
//   upd: h += relu([h|agg] @ uW + ub); epilogue zeroes agg for next layer
// ---------------------------------------------------------------------------

#define NN_MAX 100000
#define NE_MAX 600000

// scratch (allocation-free: __device__ globals)
__device__ float g_h   [(size_t)NN_MAX * 128];
__device__ float g_agg [(size_t)NN_MAX * 128];
__device__ float g_tmpn[(size_t)NN_MAX * 128];
__device__ float g_p1  [(size_t)NN_MAX * 128];
__device__ float g_p2  [(size_t)NN_MAX * 128];
__device__ float g_e   [(size_t)NE_MAX * 128];
__device__ float g_tmpe[(size_t)NE_MAX * 128];
__device__ float g_zbias[128];   // zero-initialized, never written

// ---------------------------------------------------------------------------
__global__ void zero_kernel(float* __restrict__ p, int n4) {
    int i = blockIdx.x * blockDim.x + threadIdx.x;
    if (i < n4) reinterpret_cast<float4*>(p)[i] = make_float4(0.f, 0.f, 0.f, 0.f);
}

// ---------------------------------------------------------------------------
// tiny-K first linear + relu
__global__ void mlp1_kernel(const float* __restrict__ X, const float* __restrict__ W,
                            const float* __restrict__ b, float* __restrict__ out, int K) {
    int row = blockIdx.x;
    int col = threadIdx.x;
    float acc = b[col];
    const float* xr = X + (size_t)row * K;
    for (int k = 0; k < K; ++k)
        acc += xr[k] * W[k * 128 + col];
    out[(size_t)row * 128 + col] = fmaxf(acc, 0.f);
}

// ---------------------------------------------------------------------------
__device__ __forceinline__ void red_add_v4(float* addr, float a, float b, float c, float d) {
    asm volatile("red.global.add.v4.f32 [%0], {%1,%2,%3,%4};"
                 :: "l"(addr), "f"(a), "f"(b), "f"(c), "f"(d) : "memory");
}

// ---------------------------------------------------------------------------
// Fused tiled GEMM: BM=128, BN=128(=H), BK=16, 256 threads, 8x8 register tile.
// MODE: 0 plain A (MxK, ld=K) | 2 upd concat [h|agg] (K=256)
// EPI : 0 store (opt relu)
//       2 residual Cout[m] += relu(v), and zero AGGZ[m] row
//       3 msg: v = relu(acc + bias + P1[src[m]] + P2[dst[m]]), RED into Cout[dst[m]]
#define GBM 128
#define GBK 16

template<int MODE>
__device__ __forceinline__ void load_tile_regs(
    const float* __restrict__ A, const float* __restrict__ W,
    const float* __restrict__ H, const float* __restrict__ E_,
    int m0, int M, int K, int kbase, int t,
    float4 wv[2], float4 av[2])
{
#pragma unroll
    for (int r = 0; r < 2; ++r) {
        int id = t + r * 256;
        int kk = id >> 5;
        int c4 = (id & 31) * 4;
        wv[r] = *reinterpret_cast<const float4*>(&W[(size_t)(kbase + kk) * 128 + c4]);
    }
#pragma unroll
    for (int r = 0; r < 2; ++r) {
        int id  = t + r * 256;
        int row = id >> 2;
        int kq  = (id & 3) * 4;
        int m   = m0 + row;
        int mc  = m < M ? m : M - 1;
        int k   = kbase + kq;
        const float* base;
        if (MODE == 0) {
            base = &A[(size_t)mc * K + k];
        } else {
            if (k < 128) base = &H [(size_t)mc * 128 + k];
            else         base = &E_[(size_t)mc * 128 + (k - 128)];
        }
        av[r] = *reinterpret_cast<const float4*>(base);
    }
}

template<int MODE, int EPI, bool RELU>
__global__ __launch_bounds__(256)
void gemm128(const float* __restrict__ A, const float* __restrict__ W,
             const float* __restrict__ bias, float* __restrict__ Cout,
             const int* __restrict__ src, const int* __restrict__ dst,
             const float* __restrict__ H, const float* __restrict__ E_,
             float* __restrict__ AGGZ,
             int M, int K)
{
    __shared__ float As[GBK][GBM + 4];
    __shared__ float Ws[GBK][128];

    const int t  = threadIdx.x;
    const int tx = t & 15;
    const int ty = t >> 4;
    const int m0 = blockIdx.x * GBM;
    const int nchunks = K / GBK;

    float acc[8][8];
#pragma unroll
    for (int i = 0; i < 8; ++i)
#pragma unroll
        for (int j = 0; j < 8; ++j) acc[i][j] = 0.f;

    float4 wv[2], av[2];
    load_tile_regs<MODE>(A, W, H, E_, m0, M, K, 0, t, wv, av);

    for (int ch = 0; ch < nchunks; ++ch) {
#pragma unroll
        for (int r = 0; r < 2; ++r) {
            int id = t + r * 256;
            int kk = id >> 5;
            int c4 = (id & 31) * 4;
            *reinterpret_cast<float4*>(&Ws[kk][c4]) = wv[r];
            int row = id >> 2;
            int kq  = (id & 3) * 4;
            As[kq + 0][row] = av[r].x;
            As[kq + 1][row] = av[r].y;
            As[kq + 2][row] = av[r].z;
            As[kq + 3][row] = av[r].w;
        }
        __syncthreads();
        if (ch + 1 < nchunks)
            load_tile_regs<MODE>(A, W, H, E_, m0, M, K, (ch + 1) * GBK, t, wv, av);

#pragma unroll
        for (int k = 0; k < GBK; ++k) {
            float4 a0 = *reinterpret_cast<const float4*>(&As[k][ty * 8]);
            float4 a1 = *reinterpret_cast<const float4*>(&As[k][ty * 8 + 4]);
            float4 b0 = *reinterpret_cast<const float4*>(&Ws[k][tx * 8]);
            float4 b1 = *reinterpret_cast<const float4*>(&Ws[k][tx * 8 + 4]);
            float a[8] = {a0.x, a0.y, a0.z, a0.w, a1.x, a1.y, a1.z, a1.w};
            float b[8] = {b0.x, b0.y, b0.z, b0.w, b1.x, b1.y, b1.z, b1.w};
#pragma unroll
            for (int i = 0; i < 8; ++i)
#pragma unroll
                for (int j = 0; j < 8; ++j)
                    acc[i][j] += a[i] * b[j];
        }
        __syncthreads();
    }

    // epilogue
#pragma unroll
    for (int i = 0; i < 8; ++i) {
        int m = m0 + ty * 8 + i;
        if (m >= M) continue;
        float raw[8];
#pragma unroll
        for (int j = 0; j < 8; ++j) raw[j] = acc[i][j] + bias[tx * 8 + j];

        if (EPI == 0) {
            float* cp = &Cout[(size_t)m * 128 + tx * 8];
            float v[8];
#pragma unroll
            for (int j = 0; j < 8; ++j) v[j] = RELU ? fmaxf(raw[j], 0.f) : raw[j];
            *reinterpret_cast<float4*>(cp)     = make_float4(v[0], v[1], v[2], v[3]);
            *reinterpret_cast<float4*>(cp + 4) = make_float4(v[4], v[5], v[6], v[7]);
        } else if (EPI == 2) {
            float* cp = &Cout[(size_t)m * 128 + tx * 8];
            float4 o0 = *reinterpret_cast<const float4*>(cp);
            float4 o1 = *reinterpret_cast<const float4*>(cp + 4);
            o0.x += fmaxf(raw[0], 0.f); o0.y += fmaxf(raw[1], 0.f);
            o0.z += fmaxf(raw[2], 0.f); o0.w += fmaxf(raw[3], 0.f);
            o1.x += fmaxf(raw[4], 0.f); o1.y += fmaxf(raw[5], 0.f);
            o1.z += fmaxf(raw[6], 0.f); o1.w += fmaxf(raw[7], 0.f);
            *reinterpret_cast<float4*>(cp)     = o0;
            *reinterpret_cast<float4*>(cp + 4) = o1;
            // zero the agg row for the next layer (only this block touches row m)
            float4 z = make_float4(0.f, 0.f, 0.f, 0.f);
            float* zp = &AGGZ[(size_t)m * 128 + tx * 8];
            *reinterpret_cast<float4*>(zp)     = z;
            *reinterpret_cast<float4*>(zp + 4) = z;
        } else {  // EPI == 3: fused edge combine + scatter
            int s = __ldg(&src[m]);
            int d = __ldg(&dst[m]);
            const float* p1 = &H [(size_t)s * 128 + tx * 8];
            const float* p2 = &E_[(size_t)d * 128 + tx * 8];
            float4 a0 = __ldg(reinterpret_cast<const float4*>(p1));
            float4 a1 = __ldg(reinterpret_cast<const float4*>(p1 + 4));
            float4 b0 = __ldg(reinterpret_cast<const float4*>(p2));
            float4 b1 = __ldg(reinterpret_cast<const float4*>(p2 + 4));
            float v0 = fmaxf(raw[0] + a0.x + b0.x, 0.f);
            float v1 = fmaxf(raw[1] + a0.y + b0.y, 0.f);
            float v2 = fmaxf(raw[2] + a0.z + b0.z, 0.f);
            float v3 = fmaxf(raw[3] + a0.w + b0.w, 0.f);
            float v4 = fmaxf(raw[4] + a1.x + b1.x, 0.f);
            float v5 = fmaxf(raw[5] + a1.y + b1.y, 0.f);
            float v6 = fmaxf(raw[6] + a1.z + b1.z, 0.f);
            float v7 = fmaxf(raw[7] + a1.w + b1.w, 0.f);
            float* base = &Cout[(size_t)d * 128 + tx * 8];
            red_add_v4(base,     v0, v1, v2, v3);
            red_add_v4(base + 4, v4, v5, v6, v7);
        }
    }
}

// ---------------------------------------------------------------------------
// fused decoder tail
__global__ void dec2_kernel(const float* __restrict__ f1, const float* __restrict__ W2,
                            const float* __restrict__ b2, const float* __restrict__ W3,
                            const float* __restrict__ b3, const float* __restrict__ bc_disp,
                            const float* __restrict__ bc_rot, const float* __restrict__ face_mask,
                            float* __restrict__ out, int N)
{
    __shared__ float W2s[128 * 64];
    __shared__ float W3s[64 * 15];
    __shared__ float b2s[64], b3s[16];
    __shared__ float f1s[2][128];
    __shared__ float f2s[2][64];

    int t = threadIdx.x;  // 128
    for (int i = t; i < 128 * 64; i += 128) W2s[i] = W2[i];
    for (int i = t; i < 64 * 15;  i += 128) W3s[i] = W3[i];
    if (t < 64) b2s[t] = b2[t];
    if (t < 15) b3s[t] = b3[t];
    __syncthreads();

    int base = blockIdx.x * 64;
    for (int it = 0; it < 32; ++it) {
        int n0 = base + it * 2;
#pragma unroll
        for (int r = 0; r < 2; ++r) {
            int n = n0 + r;
            f1s[r][t] = (n < N) ? f1[(size_t)n * 128 + t] : 0.f;
        }
        __syncthreads();
        {
            int rn = t >> 6, j = t & 63;
            float acc = b2s[j];
#pragma unroll 8
            for (int k = 0; k < 128; ++k) acc += f1s[rn][k] * W2s[k * 64 + j];
            f2s[rn][j] = fmaxf(acc, 0.f);
        }
        __syncthreads();
        if (t < 30) {
            int rr = t / 15, c = t % 15;
            int n = n0 + rr;
            if (n < N) {
                float acc = b3s[c];
#pragma unroll 8
                for (int k = 0; k < 64; ++k) acc += f2s[rr][k] * W3s[k * 15 + c];
                float mask;
                if (c < 2)       mask = 1.f - bc_disp[n];
                else if (c == 2) mask = 1.f - bc_rot[n];
                else             mask = face_mask[(size_t)n * 4 + (c - 3) / 3];
                out[(size_t)n * 15 + c] = acc * mask;
            }
        }
        __syncthreads();
    }
}

// ---------------------------------------------------------------------------
extern "C" void kernel_launch(void* const* d_in, const int* in_sizes, int n_in,
                              void* d_out, int out_size)
{
    const float* x         = (const float*)d_in[0];
    const float* edge_attr = (const float*)d_in[1];
    const int*   edge_idx  = (const int*)  d_in[2];
    const float* bc_disp   = (const float*)d_in[3];
    const float* bc_rot    = (const float*)d_in[4];
    const float* face_mask = (const float*)d_in[5];
    const float* enc_n_W1  = (const float*)d_in[6];
    const float* enc_n_b1  = (const float*)d_in[7];
    const float* enc_n_W2  = (const float*)d_in[8];
    const float* enc_n_b2  = (const float*)d_in[9];
    const float* enc_e_W1  = (const float*)d_in[10];
    const float* enc_e_b1  = (const float*)d_in[11];
    const float* enc_e_W2  = (const float*)d_in[12];
    const float* enc_e_b2  = (const float*)d_in[13];
    const float* msg_W     = (const float*)d_in[14];
    const float* msg_b     = (const float*)d_in[15];
    const float* upd_W     = (const float*)d_in[16];
    const float* upd_b     = (const float*)d_in[17];
    const float* dec_W1    = (const float*)d_in[18];
    const float* dec_b1    = (const float*)d_in[19];
    const float* dec_W2    = (const float*)d_in[20];
    const float* dec_b2    = (const float*)d_in[21];
    const float* dec_W3    = (const float*)d_in[22];
    const float* dec_b3    = (const float*)d_in[23];

    const int N = in_sizes[0] / 9;
    const int E = in_sizes[1] / 10;
    const int* src = edge_idx;
    const int* dst = edge_idx + E;

    float *h, *agg, *tmpn, *e, *tmpe, *p1, *p2, *zb;
    cudaGetSymbolAddress((void**)&h,    g_h);
    cudaGetSymbolAddress((void**)&agg,  g_agg);
    cudaGetSymbolAddress((void**)&tmpn, g_tmpn);
    cudaGetSymbolAddress((void**)&e,    g_e);
    cudaGetSymbolAddress((void**)&tmpe, g_tmpe);
    cudaGetSymbolAddress((void**)&p1,   g_p1);
    cudaGetSymbolAddress((void**)&p2,   g_p2);
    cudaGetSymbolAddress((void**)&zb,   g_zbias);

    const int gN = (N + 127) / 128;
    const int gE = (E + 127) / 128;

    // encoders
    mlp1_kernel<<<N, 128>>>(x, enc_n_W1, enc_n_b1, tmpn, 9);
    gemm128<0, 0, false><<<gN, 256>>>(tmpn, enc_n_W2, enc_n_b2, h,
                                      nullptr, nullptr, nullptr, nullptr, nullptr, N, 128);
    mlp1_kernel<<<E, 128>>>(edge_attr, enc_e_W1, enc_e_b1, tmpe, 10);
    gemm128<0, 0, false><<<gE, 256>>>(tmpe, enc_e_W2, enc_e_b2, e,
                                      nullptr, nullptr, nullptr, nullptr, nullptr, E, 128);

    // agg = 0 (subsequent layers get it zeroed by the upd epilogue)
    zero_kernel<<<(N * 128 / 4 + 255) / 256, 256>>>(agg, N * 128 / 4);

    // message-passing layers
    for (int l = 0; l < 6; ++l) {
        const float* mW = msg_W + (size_t)l * 384 * 128;
        // P1 = h @ mW1, P2 = h @ mW2
        gemm128<0, 0, false><<<gN, 256>>>(h, mW, zb, p1,
                                          nullptr, nullptr, nullptr, nullptr, nullptr, N, 128);
        gemm128<0, 0, false><<<gN, 256>>>(h, mW + 128 * 128, zb, p2,
                                          nullptr, nullptr, nullptr, nullptr, nullptr, N, 128);
        // msg-GEMM: acc = e @ mW3, epilogue gathers P1[src], P2[dst], relu, RED into agg[dst]
        gemm128<0, 3, true><<<gE, 256>>>(e, mW + 256 * 128, msg_b + l * 128, agg,
                                         src, dst, p1, p2, nullptr, E, 128);
        // upd: h += relu([h|agg] @ uW + ub), zero agg for next layer
        gemm128<2, 2, true><<<gN, 256>>>(nullptr, upd_W + (size_t)l * 256 * 128,
                                         upd_b + l * 128, h,
                                         nullptr, nullptr, h, agg, agg, N, 256);
    }

    // decoder
    gemm128<0, 0, true><<<gN, 256>>>(h, dec_W1, dec_b1, tmpn,
                                     nullptr, nullptr, nullptr, nullptr, nullptr, N, 128);
    dec2_kernel<<<(N + 63) / 64, 128>>>(tmpn, dec_W2, dec_b2, dec_W3, dec_b3,
                                        bc_disp, bc_rot, face_mask, (float*)d_out, N);
}

// round 5
// speedup vs baseline: 2.0089x; 1.4156x over previous
#include <cuda_runtime.h>
#include <cuda_bf16.h>
#include <cstdint>

// ===========================================================================
// PIGNN forward — mma.sync (sm_100 base target) bf16 hi/lo split GEMMs.
//
//   msg_in @ mW == h[src]@mW1 + h[dst]@mW2 + e@mW3
//   per layer:  P1=h@mW1, P2=h@mW2
//               msg: acc=e@mW3; epi: relu(acc+b+P1[src]+P2[dst]) RED-> agg[dst]
//               upd: h += relu([h|agg]@uW+ub); epi zeroes agg
// ===========================================================================

#define NN_MAX 100000
#define NE_MAX 600000

__device__ float g_h   [(size_t)NN_MAX * 128];
__device__ float g_agg [(size_t)NN_MAX * 128];
__device__ float g_tmpn[(size_t)NN_MAX * 128];
__device__ float g_p1  [(size_t)NN_MAX * 128];
__device__ float g_p2  [(size_t)NN_MAX * 128];
__device__ float g_tmpe[(size_t)NE_MAX * 128];
__device__ __nv_bfloat16 g_ehi[(size_t)NE_MAX * 128];
__device__ __nv_bfloat16 g_elo[(size_t)NE_MAX * 128];
// weights transposed to [N=128, K] row-major, split hi/lo:
//   21 mats K=128 (encN, encE, decW1, 6x{mW1,mW2,mW3}) then 6 upd mats K=256
#define W128_CNT 21
#define WUPD_OFF (W128_CNT * 16384)
#define WTOT (WUPD_OFF + 6 * 32768)
__device__ __nv_bfloat16 g_whi[WTOT];
__device__ __nv_bfloat16 g_wlo[WTOT];
__device__ float g_zbias[128];   // zero-initialized, never written

// ---------------------------------------------------------------------------
__device__ __forceinline__ uint32_t smem_to_u32(const void* p) {
    uint32_t a;
    asm("{ .reg .u64 t; cvta.to.shared.u64 t, %1; cvt.u32.u64 %0, t; }" : "=r"(a) : "l"(p));
    return a;
}
__device__ __forceinline__ void ldmx4(uint32_t& r0, uint32_t& r1, uint32_t& r2, uint32_t& r3,
                                      uint32_t addr) {
    asm volatile("ldmatrix.sync.aligned.m8n8.x4.shared.b16 {%0,%1,%2,%3}, [%4];"
                 : "=r"(r0), "=r"(r1), "=r"(r2), "=r"(r3) : "r"(addr));
}
__device__ __forceinline__ void mma_bf16(float& c0, float& c1, float& c2, float& c3,
                                         uint32_t a0, uint32_t a1, uint32_t a2, uint32_t a3,
                                         uint32_t b0, uint32_t b1) {
    asm volatile("mma.sync.aligned.m16n8k16.row.col.f32.bf16.bf16.f32 "
                 "{%0,%1,%2,%3}, {%4,%5,%6,%7}, {%8,%9}, {%0,%1,%2,%3};"
                 : "+f"(c0), "+f"(c1), "+f"(c2), "+f"(c3)
                 : "r"(a0), "r"(a1), "r"(a2), "r"(a3), "r"(b0), "r"(b1));
}
__device__ __forceinline__ void red_add_v4(float* addr, float a, float b, float c, float d) {
    asm volatile("red.global.add.v4.f32 [%0], {%1,%2,%3,%4};"
                 :: "l"(addr), "f"(a), "f"(b), "f"(c), "f"(d) : "memory");
}
__device__ __forceinline__ uint32_t pack_bf2(float a, float b) {
    __nv_bfloat162 v = __floats2bfloat162_rn(a, b);
    return *reinterpret_cast<uint32_t*>(&v);
}
__device__ __forceinline__ void split4(const float4 v, uint32_t& h01, uint32_t& h23,
                                       uint32_t& l01, uint32_t& l23) {
    __nv_bfloat16 h0 = __float2bfloat16(v.x), h1 = __float2bfloat16(v.y);
    __nv_bfloat16 h2 = __float2bfloat16(v.z), h3 = __float2bfloat16(v.w);
    float l0 = v.x - __bfloat162float(h0), l1 = v.y - __bfloat162float(h1);
    float l2 = v.z - __bfloat162float(h2), l3 = v.w - __bfloat162float(h3);
    __nv_bfloat162 hh0 = __nv_bfloat162(h0, h1), hh1 = __nv_bfloat162(h2, h3);
    h01 = *reinterpret_cast<uint32_t*>(&hh0);
    h23 = *reinterpret_cast<uint32_t*>(&hh1);
    l01 = pack_bf2(l0, l1);
    l23 = pack_bf2(l2, l3);
}

// ---------------------------------------------------------------------------
// SMEM layout: 4 bf16 slabs [128][64] with row stride 72 bf16 (144B),
// overlaid by C float[128][132] after the mainloop, + bias.
#define SA 72
#define SLAB_BYTES (128 * SA * 2)           // 18432
#define OFF_AHI 0
#define OFF_ALO (SLAB_BYTES)
#define OFF_BHI (2 * SLAB_BYTES)
#define OFF_BLO (3 * SLAB_BYTES)
#define OFF_BIAS (4 * SLAB_BYTES)           // 73728
#define SMEM_BYTES (OFF_BIAS + 512 + 16)
#define CSTRIDE 132

// ---------------------------------------------------------------------------
// mma.sync GEMM: tile 128x128, K-slab 64, 3-pass bf16 split, 256 thr (8 warps 4x2).
// MODE: 0 A=fp32 [M,K] | 1 A=pre-split bf16 (Ahi/Alo, ld=128) | 2 A=[h|agg] fp32, K=256
// EPI : 0 store fp32 (RELU opt) | 1 store bf16 hi/lo | 2 h+=relu, zero agg | 3 msg RED
template<int MODE, int EPI, bool RELU>
__global__ __launch_bounds__(256)
void mmagemm(const float* __restrict__ Af, const float* __restrict__ Af2,
             const __nv_bfloat16* __restrict__ Ahi, const __nv_bfloat16* __restrict__ Alo,
             const __nv_bfloat16* __restrict__ Bhi, const __nv_bfloat16* __restrict__ Blo,
             const float* __restrict__ bias,
             float* __restrict__ Cout, __nv_bfloat16* __restrict__ OutHi,
             __nv_bfloat16* __restrict__ OutLo,
             const int* __restrict__ src, const int* __restrict__ dst,
             const float* __restrict__ P1, const float* __restrict__ P2,
             float* __restrict__ AGGZ,
             int M, int K)
{
    extern __shared__ char smem[];
    const uint32_t sb = smem_to_u32(smem);
    const int t = threadIdx.x;
    const int lane = t & 31;
    const int wid = t >> 5;
    const int wm = wid & 3;          // 4 warps over 128 rows (32 each)
    const int wn = wid >> 2;         // 2 warps over 128 cols (64 each)
    float* sBias = reinterpret_cast<float*>(smem + OFF_BIAS);
    if (t < 128) sBias[t] = bias[t];

    const int m0 = blockIdx.x * 128;
    const int nslabs = K >> 6;

    float acc[2][8][4];
#pragma unroll
    for (int i = 0; i < 2; ++i)
#pragma unroll
        for (int j = 0; j < 8; ++j)
#pragma unroll
            for (int r = 0; r < 4; ++r) acc[i][j][r] = 0.f;

    for (int s = 0; s < nslabs; ++s) {
        const int kb = s << 6;
        __syncthreads();   // protect smem from prior slab's readers
        // ---- fill A slab: 128 rows x 64 bf16 (hi & lo) ----
#pragma unroll
        for (int i = 0; i < 8; ++i) {
            int id = t + i * 256;
            int row = id >> 4;          // 16 quads per row
            int q = id & 15;
            int m = m0 + row;
            int mc = m < M ? m : M - 1;
            uint32_t off = (uint32_t)row * 144 + q * 8;
            if (MODE == 1) {
                size_t eidx = ((size_t)mc * 128 + kb + q * 4) >> 2;
                *reinterpret_cast<uint2*>(smem + OFF_AHI + off) =
                    reinterpret_cast<const uint2*>(Ahi)[eidx];
                *reinterpret_cast<uint2*>(smem + OFF_ALO + off) =
                    reinterpret_cast<const uint2*>(Alo)[eidx];
            } else {
                float4 v;
                if (MODE == 0) {
                    v = *reinterpret_cast<const float4*>(&Af[(size_t)mc * K + kb + q * 4]);
                } else {
                    int kg = kb + q * 4;
                    const float* base = (kg < 128) ? &Af[(size_t)mc * 128 + kg]
                                                   : &Af2[(size_t)mc * 128 + (kg - 128)];
                    v = *reinterpret_cast<const float4*>(base);
                }
                uint32_t h01, h23, l01, l23;
                split4(v, h01, h23, l01, l23);
                *reinterpret_cast<uint2*>(smem + OFF_AHI + off) = make_uint2(h01, h23);
                *reinterpret_cast<uint2*>(smem + OFF_ALO + off) = make_uint2(l01, l23);
            }
        }
        // ---- fill B slab: 128 n-rows x 64 k (hi & lo), source ld = K ----
#pragma unroll
        for (int i = 0; i < 8; ++i) {
            int id = t + i * 256;
            int row = id >> 4;
            int q = id & 15;
            size_t bidx = ((size_t)row * K + kb + q * 4) >> 2;
            uint32_t off = (uint32_t)row * 144 + q * 8;
            *reinterpret_cast<uint2*>(smem + OFF_BHI + off) =
                reinterpret_cast<const uint2*>(Bhi)[bidx];
            *reinterpret_cast<uint2*>(smem + OFF_BLO + off) =
                reinterpret_cast<const uint2*>(Blo)[bidx];
        }
        __syncthreads();

        // ---- compute: 4 k16-steps, 3 split passes ----
#pragma unroll
        for (int ks = 0; ks < 4; ++ks) {
            // A fragments (hi & lo) for 2 m16 tiles
            uint32_t ahi[2][4], alo[2][4];
            {
                uint32_t arow = wm * 32 + (lane & 15);
                uint32_t kcol = ks * 16 + (lane >> 4) * 8;
#pragma unroll
                for (int i = 0; i < 2; ++i) {
                    uint32_t off = (arow + i * 16) * 144 + kcol * 2;
                    ldmx4(ahi[i][0], ahi[i][1], ahi[i][2], ahi[i][3], sb + OFF_AHI + off);
                    ldmx4(alo[i][0], alo[i][1], alo[i][2], alo[i][3], sb + OFF_ALO + off);
                }
            }
            // B fragments in pairs of n8 tiles
            uint32_t nrow = wn * 64 + (lane & 7) + (lane >> 4) * 8;
            uint32_t koff = ks * 16 + ((lane >> 3) & 1) * 8;
#pragma unroll
            for (int j2 = 0; j2 < 4; ++j2) {
                uint32_t off = (nrow + j2 * 16) * 144 + koff * 2;
                uint32_t bh[4], bl[4];
                ldmx4(bh[0], bh[1], bh[2], bh[3], sb + OFF_BHI + off);
                ldmx4(bl[0], bl[1], bl[2], bl[3], sb + OFF_BLO + off);
#pragma unroll
                for (int i = 0; i < 2; ++i) {
#pragma unroll
                    for (int jj = 0; jj < 2; ++jj) {
                        int jn = j2 * 2 + jj;
                        float* c = acc[i][jn];
                        mma_bf16(c[0], c[1], c[2], c[3],
                                 ahi[i][0], ahi[i][1], ahi[i][2], ahi[i][3],
                                 bh[jj * 2], bh[jj * 2 + 1]);
                        mma_bf16(c[0], c[1], c[2], c[3],
                                 alo[i][0], alo[i][1], alo[i][2], alo[i][3],
                                 bh[jj * 2], bh[jj * 2 + 1]);
                        mma_bf16(c[0], c[1], c[2], c[3],
                                 ahi[i][0], ahi[i][1], ahi[i][2], ahi[i][3],
                                 bl[jj * 2], bl[jj * 2 + 1]);
                    }
                }
            }
        }
    }

    // ---- stage C through smem (overlays the operand slabs) ----
    __syncthreads();
    float* Cs = reinterpret_cast<float*>(smem);
#pragma unroll
    for (int i = 0; i < 2; ++i)
#pragma unroll
        for (int jn = 0; jn < 8; ++jn)
#pragma unroll
            for (int r = 0; r < 4; ++r) {
                int row = wm * 32 + i * 16 + (lane >> 2) + (r >= 2 ? 8 : 0);
                int col = wn * 64 + jn * 8 + (lane & 3) * 2 + (r & 1);
                Cs[row * CSTRIDE + col] = acc[i][jn][r];
            }
    __syncthreads();

    // ---- epilogue: thread t owns row t>>1, cols (t&1)*64 .. +63 ----
    {
        const int row = t >> 1;
        const int cb = (t & 1) * 64;
        const int m = m0 + row;
        if (m < M) {
            const float* crow = &Cs[row * CSTRIDE + cb];
            int sI = 0, dI = 0;
            if (EPI == 3) { sI = __ldg(&src[m]); dI = __ldg(&dst[m]); }
#pragma unroll
            for (int q = 0; q < 16; ++q) {
                float v0 = crow[q*4+0] + sBias[cb + q*4+0];
                float v1 = crow[q*4+1] + sBias[cb + q*4+1];
                float v2 = crow[q*4+2] + sBias[cb + q*4+2];
                float v3 = crow[q*4+3] + sBias[cb + q*4+3];
                if (EPI == 0) {
                    if (RELU) { v0 = fmaxf(v0,0.f); v1 = fmaxf(v1,0.f);
                                v2 = fmaxf(v2,0.f); v3 = fmaxf(v3,0.f); }
                    reinterpret_cast<float4*>(&Cout[(size_t)m * 128 + cb])[q] =
                        make_float4(v0, v1, v2, v3);
                } else if (EPI == 1) {
                    __nv_bfloat16 h0 = __float2bfloat16(v0), h1 = __float2bfloat16(v1);
                    __nv_bfloat16 h2 = __float2bfloat16(v2), h3 = __float2bfloat16(v3);
                    float l0 = v0 - __bfloat162float(h0), l1 = v1 - __bfloat162float(h1);
                    float l2 = v2 - __bfloat162float(h2), l3 = v3 - __bfloat162float(h3);
                    __nv_bfloat162 hp0 = __nv_bfloat162(h0, h1), hp1 = __nv_bfloat162(h2, h3);
                    uint2 hu = make_uint2(*reinterpret_cast<uint32_t*>(&hp0),
                                          *reinterpret_cast<uint32_t*>(&hp1));
                    uint2 lu = make_uint2(pack_bf2(l0, l1), pack_bf2(l2, l3));
                    reinterpret_cast<uint2*>(OutHi + (size_t)m * 128 + cb)[q] = hu;
                    reinterpret_cast<uint2*>(OutLo + (size_t)m * 128 + cb)[q] = lu;
                } else if (EPI == 2) {
                    float* cp = &Cout[(size_t)m * 128 + cb];
                    float4 o = reinterpret_cast<float4*>(cp)[q];
                    o.x += fmaxf(v0, 0.f); o.y += fmaxf(v1, 0.f);
                    o.z += fmaxf(v2, 0.f); o.w += fmaxf(v3, 0.f);
                    reinterpret_cast<float4*>(cp)[q] = o;
                    reinterpret_cast<float4*>(&AGGZ[(size_t)m * 128 + cb])[q] =
                        make_float4(0.f, 0.f, 0.f, 0.f);
                } else {
                    const float4 a = __ldg(&reinterpret_cast<const float4*>(
                                               &P1[(size_t)sI * 128 + cb])[q]);
                    const float4 b = __ldg(&reinterpret_cast<const float4*>(
                                               &P2[(size_t)dI * 128 + cb])[q]);
                    float x0 = fmaxf(v0 + a.x + b.x, 0.f);
                    float x1 = fmaxf(v1 + a.y + b.y, 0.f);
                    float x2 = fmaxf(v2 + a.z + b.z, 0.f);
                    float x3 = fmaxf(v3 + a.w + b.w, 0.f);
                    red_add_v4(&AGGZ[(size_t)dI * 128 + cb + q * 4], x0, x1, x2, x3);
                }
            }
        }
    }
}

// ---------------------------------------------------------------------------
// weight prep: transpose [K,128]->[128,K] and split into bf16 hi/lo
struct PtrTab { const float* p[W128_CNT]; };

__global__ void prep_w128(PtrTab tab, __nv_bfloat16* __restrict__ hi, __nv_bfloat16* __restrict__ lo) {
    int mat = blockIdx.y;
    int i = blockIdx.x * 256 + threadIdx.x;
    if (i >= 16384) return;
    int n = i >> 7, k = i & 127;
    float w = tab.p[mat][k * 128 + n];
    __nv_bfloat16 h = __float2bfloat16(w);
    hi[(size_t)mat * 16384 + i] = h;
    lo[(size_t)mat * 16384 + i] = __float2bfloat16(w - __bfloat162float(h));
}
__global__ void prep_w256(const float* __restrict__ W, __nv_bfloat16* __restrict__ hi,
                          __nv_bfloat16* __restrict__ lo) {
    int mat = blockIdx.y;
    int i = blockIdx.x * 256 + threadIdx.x;
    if (i >= 32768) return;
    int n = i >> 8, k = i & 255;
    float w = W[(size_t)mat * 256 * 128 + k * 128 + n];
    __nv_bfloat16 h = __float2bfloat16(w);
    hi[(size_t)(WUPD_OFF + mat * 32768) + i] = h;
    lo[(size_t)(WUPD_OFF + mat * 32768) + i] = __float2bfloat16(w - __bfloat162float(h));
}

// ---------------------------------------------------------------------------
__global__ void zero_kernel(float* __restrict__ p, int n4) {
    int i = blockIdx.x * blockDim.x + threadIdx.x;
    if (i < n4) reinterpret_cast<float4*>(p)[i] = make_float4(0.f, 0.f, 0.f, 0.f);
}

__global__ void mlp1_kernel(const float* __restrict__ X, const float* __restrict__ W,
                            const float* __restrict__ b, float* __restrict__ out, int K) {
    int row = blockIdx.x;
    int col = threadIdx.x;
    float acc = b[col];
    const float* xr = X + (size_t)row * K;
    for (int k = 0; k < K; ++k)
        acc += xr[k] * W[k * 128 + col];
    out[(size_t)row * 128 + col] = fmaxf(acc, 0.f);
}

// fused decoder tail
__global__ void dec2_kernel(const float* __restrict__ f1, const float* __restrict__ W2,
                            const float* __restrict__ b2, const float* __restrict__ W3,
                            const float* __restrict__ b3, const float* __restrict__ bc_disp,
                            const float* __restrict__ bc_rot, const float* __restrict__ face_mask,
                            float* __restrict__ out, int N)
{
    __shared__ float W2s[128 * 64];
    __shared__ float W3s[64 * 15];
    __shared__ float b2s[64], b3s[16];
    __shared__ float f1s[2][128];
    __shared__ float f2s[2][64];

    int t = threadIdx.x;
    for (int i = t; i < 128 * 64; i += 128) W2s[i] = W2[i];
    for (int i = t; i < 64 * 15;  i += 128) W3s[i] = W3[i];
    if (t < 64) b2s[t] = b2[t];
    if (t < 15) b3s[t] = b3[t];
    __syncthreads();

    int base = blockIdx.x * 64;
    for (int it = 0; it < 32; ++it) {
        int n0 = base + it * 2;
#pragma unroll
        for (int r = 0; r < 2; ++r) {
            int n = n0 + r;
            f1s[r][t] = (n < N) ? f1[(size_t)n * 128 + t] : 0.f;
        }
        __syncthreads();
        {
            int rn = t >> 6, j = t & 63;
            float acc = b2s[j];
#pragma unroll 8
            for (int k = 0; k < 128; ++k) acc += f1s[rn][k] * W2s[k * 64 + j];
            f2s[rn][j] = fmaxf(acc, 0.f);
        }
        __syncthreads();
        if (t < 30) {
            int rr = t / 15, c = t % 15;
            int n = n0 + rr;
            if (n < N) {
                float acc = b3s[c];
#pragma unroll 8
                for (int k = 0; k < 64; ++k) acc += f2s[rr][k] * W3s[k * 15 + c];
                float mask;
                if (c < 2)       mask = 1.f - bc_disp[n];
                else if (c == 2) mask = 1.f - bc_rot[n];
                else             mask = face_mask[(size_t)n * 4 + (c - 3) / 3];
                out[(size_t)n * 15 + c] = acc * mask;
            }
        }
        __syncthreads();
    }
}

// ---------------------------------------------------------------------------
extern "C" void kernel_launch(void* const* d_in, const int* in_sizes, int n_in,
                              void* d_out, int out_size)
{
    const float* x         = (const float*)d_in[0];
    const float* edge_attr = (const float*)d_in[1];
    const int*   edge_idx  = (const int*)  d_in[2];
    const float* bc_disp   = (const float*)d_in[3];
    const float* bc_rot    = (const float*)d_in[4];
    const float* face_mask = (const float*)d_in[5];
    const float* enc_n_W1  = (const float*)d_in[6];
    const float* enc_n_b1  = (const float*)d_in[7];
    const float* enc_n_W2  = (const float*)d_in[8];
    const float* enc_n_b2  = (const float*)d_in[9];
    const float* enc_e_W1  = (const float*)d_in[10];
    const float* enc_e_b1  = (const float*)d_in[11];
    const float* enc_e_W2  = (const float*)d_in[12];
    const float* enc_e_b2  = (const float*)d_in[13];
    const float* msg_W     = (const float*)d_in[14];
    const float* msg_b     = (const float*)d_in[15];
    const float* upd_W     = (const float*)d_in[16];
    const float* upd_b     = (const float*)d_in[17];
    const float* dec_W1    = (const float*)d_in[18];
    const float* dec_b1    = (const float*)d_in[19];
    const float* dec_W2    = (const float*)d_in[20];
    const float* dec_b2    = (const float*)d_in[21];
    const float* dec_W3    = (const float*)d_in[22];
    const float* dec_b3    = (const float*)d_in[23];

    const int N = in_sizes[0] / 9;
    const int E = in_sizes[1] / 10;
    const int* src = edge_idx;
    const int* dst = edge_idx + E;

    float *h, *agg, *tmpn, *tmpe, *p1, *p2, *zb;
    __nv_bfloat16 *ehi, *elo, *whi, *wlo;
    cudaGetSymbolAddress((void**)&h,    g_h);
    cudaGetSymbolAddress((void**)&agg,  g_agg);
    cudaGetSymbolAddress((void**)&tmpn, g_tmpn);
    cudaGetSymbolAddress((void**)&tmpe, g_tmpe);
    cudaGetSymbolAddress((void**)&p1,   g_p1);
    cudaGetSymbolAddress((void**)&p2,   g_p2);
    cudaGetSymbolAddress((void**)&zb,   g_zbias);
    cudaGetSymbolAddress((void**)&ehi,  g_ehi);
    cudaGetSymbolAddress((void**)&elo,  g_elo);
    cudaGetSymbolAddress((void**)&whi,  g_whi);
    cudaGetSymbolAddress((void**)&wlo,  g_wlo);

    cudaFuncSetAttribute((const void*)mmagemm<0,0,false>, cudaFuncAttributeMaxDynamicSharedMemorySize, SMEM_BYTES);
    cudaFuncSetAttribute((const void*)mmagemm<0,0,true>,  cudaFuncAttributeMaxDynamicSharedMemorySize, SMEM_BYTES);
    cudaFuncSetAttribute((const void*)mmagemm<0,1,false>, cudaFuncAttributeMaxDynamicSharedMemorySize, SMEM_BYTES);
    cudaFuncSetAttribute((const void*)mmagemm<1,3,true>,  cudaFuncAttributeMaxDynamicSharedMemorySize, SMEM_BYTES);
    cudaFuncSetAttribute((const void*)mmagemm<2,2,true>,  cudaFuncAttributeMaxDynamicSharedMemorySize, SMEM_BYTES);

    // ---- weight prep ----
    PtrTab tab;
    tab.p[0] = enc_n_W2;
    tab.p[1] = enc_e_W2;
    tab.p[2] = dec_W1;
    for (int l = 0; l < 6; ++l)
        for (int j = 0; j < 3; ++j)
            tab.p[3 + l * 3 + j] = msg_W + (size_t)l * 384 * 128 + (size_t)j * 128 * 128;
    prep_w128<<<dim3(64, W128_CNT), 256>>>(tab, whi, wlo);
    prep_w256<<<dim3(128, 6), 256>>>(upd_W, whi, wlo);

    const int gN = (N + 127) / 128;
    const int gE = (E + 127) / 128;
    auto WH = [&](int j) { return whi + (size_t)j * 16384; };
    auto WL = [&](int j) { return wlo + (size_t)j * 16384; };

    // ---- encoders ----
    mlp1_kernel<<<N, 128>>>(x, enc_n_W1, enc_n_b1, tmpn, 9);
    mmagemm<0,0,false><<<gN, 256, SMEM_BYTES>>>(tmpn, nullptr, nullptr, nullptr, WH(0), WL(0),
        enc_n_b2, h, nullptr, nullptr, nullptr, nullptr, nullptr, nullptr, nullptr, N, 128);
    mlp1_kernel<<<E, 128>>>(edge_attr, enc_e_W1, enc_e_b1, tmpe, 10);
    mmagemm<0,1,false><<<gE, 256, SMEM_BYTES>>>(tmpe, nullptr, nullptr, nullptr, WH(1), WL(1),
        enc_e_b2, nullptr, ehi, elo, nullptr, nullptr, nullptr, nullptr, nullptr, E, 128);

    zero_kernel<<<(N * 128 / 4 + 255) / 256, 256>>>(agg, N * 128 / 4);

    // ---- message-passing layers ----
    for (int l = 0; l < 6; ++l) {
        int j = 3 + l * 3;
        mmagemm<0,0,false><<<gN, 256, SMEM_BYTES>>>(h, nullptr, nullptr, nullptr, WH(j), WL(j),
            zb, p1, nullptr, nullptr, nullptr, nullptr, nullptr, nullptr, nullptr, N, 128);
        mmagemm<0,0,false><<<gN, 256, SMEM_BYTES>>>(h, nullptr, nullptr, nullptr, WH(j+1), WL(j+1),
            zb, p2, nullptr, nullptr, nullptr, nullptr, nullptr, nullptr, nullptr, N, 128);
        mmagemm<1,3,true><<<gE, 256, SMEM_BYTES>>>(nullptr, nullptr, ehi, elo, WH(j+2), WL(j+2),
            msg_b + l * 128, nullptr, nullptr, nullptr, src, dst, p1, p2, agg, E, 128);
        mmagemm<2,2,true><<<gN, 256, SMEM_BYTES>>>(h, agg, nullptr, nullptr,
            whi + WUPD_OFF + (size_t)l * 32768, wlo + WUPD_OFF + (size_t)l * 32768,
            upd_b + l * 128, h, nullptr, nullptr, nullptr, nullptr, nullptr, nullptr, agg, N, 256);
    }

    // ---- decoder ----
    mmagemm<0,0,true><<<gN, 256, SMEM_BYTES>>>(h, nullptr, nullptr, nullptr, WH(2), WL(2),
        dec_b1, tmpn, nullptr, nullptr, nullptr, nullptr, nullptr, nullptr, nullptr, N, 128);
    dec2_kernel<<<(N + 63) / 64, 128>>>(tmpn, dec_W2, dec_b2, dec_W3, dec_b3,
                                        bc_disp, bc_rot, face_mask, (float*)d_out, N);
}

// round 6
// speedup vs baseline: 2.1060x; 1.0483x over previous
#include <cuda_runtime.h>
#include <cuda_bf16.h>
#include <cstdint>

// ===========================================================================
// PIGNN forward — mma.sync bf16 hi/lo split GEMMs, cp.async 2-stage pipeline.
//   msg_in @ mW == h[src]@mW1 + h[dst]@mW2 + e@mW3
// All GEMM A-operands are pre-split bf16 (hi/lo); only upd's agg half is
// fp32 split in-kernel.
// ===========================================================================

#define NN_MAX 100000
#define NE_MAX 600000

__device__ float g_h   [(size_t)NN_MAX * 128];
__device__ float g_agg [(size_t)NN_MAX * 128];
__device__ float g_f1  [(size_t)NN_MAX * 128];
__device__ float g_p1  [(size_t)NN_MAX * 128];
__device__ float g_p2  [(size_t)NN_MAX * 128];
__device__ __nv_bfloat16 g_hhi[(size_t)NN_MAX * 128];
__device__ __nv_bfloat16 g_hlo[(size_t)NN_MAX * 128];
__device__ __nv_bfloat16 g_ehi[(size_t)NE_MAX * 128];
__device__ __nv_bfloat16 g_elo[(size_t)NE_MAX * 128];
__device__ __nv_bfloat16 g_thi[(size_t)NE_MAX * 128];   // mlp1 outputs (shared node/edge)
__device__ __nv_bfloat16 g_tlo[(size_t)NE_MAX * 128];
// weights transposed to [N=128, K] row-major, split hi/lo
#define W128_CNT 21
#define WUPD_OFF (W128_CNT * 16384)
#define WTOT (WUPD_OFF + 6 * 32768)
__device__ __nv_bfloat16 g_whi[WTOT];
__device__ __nv_bfloat16 g_wlo[WTOT];
__device__ float g_zbias[128];   // zero-initialized, never written

// ---------------------------------------------------------------------------
__device__ __forceinline__ uint32_t smem_to_u32(const void* p) {
    uint32_t a;
    asm("{ .reg .u64 t; cvta.to.shared.u64 t, %1; cvt.u32.u64 %0, t; }" : "=r"(a) : "l"(p));
    return a;
}
__device__ __forceinline__ void ldmx4(uint32_t& r0, uint32_t& r1, uint32_t& r2, uint32_t& r3,
                                      uint32_t addr) {
    asm volatile("ldmatrix.sync.aligned.m8n8.x4.shared.b16 {%0,%1,%2,%3}, [%4];"
                 : "=r"(r0), "=r"(r1), "=r"(r2), "=r"(r3) : "r"(addr));
}
__device__ __forceinline__ void mma_bf16(float& c0, float& c1, float& c2, float& c3,
                                         uint32_t a0, uint32_t a1, uint32_t a2, uint32_t a3,
                                         uint32_t b0, uint32_t b1) {
    asm volatile("mma.sync.aligned.m16n8k16.row.col.f32.bf16.bf16.f32 "
                 "{%0,%1,%2,%3}, {%4,%5,%6,%7}, {%8,%9}, {%0,%1,%2,%3};"
                 : "+f"(c0), "+f"(c1), "+f"(c2), "+f"(c3)
                 : "r"(a0), "r"(a1), "r"(a2), "r"(a3), "r"(b0), "r"(b1));
}
__device__ __forceinline__ void cpa16(uint32_t saddr, const void* g) {
    asm volatile("cp.async.cg.shared.global [%0], [%1], 16;" :: "r"(saddr), "l"(g));
}
#define CP_COMMIT() asm volatile("cp.async.commit_group;" ::: "memory")
#define CP_WAIT1()  asm volatile("cp.async.wait_group 1;" ::: "memory")
#define CP_WAIT0()  asm volatile("cp.async.wait_group 0;" ::: "memory")
__device__ __forceinline__ void red_add_v4(float* addr, float a, float b, float c, float d) {
    asm volatile("red.global.add.v4.f32 [%0], {%1,%2,%3,%4};"
                 :: "l"(addr), "f"(a), "f"(b), "f"(c), "f"(d) : "memory");
}
__device__ __forceinline__ uint32_t pack_bf2(float a, float b) {
    __nv_bfloat162 v = __floats2bfloat162_rn(a, b);
    return *reinterpret_cast<uint32_t*>(&v);
}
__device__ __forceinline__ void split4(const float4 v, uint32_t& h01, uint32_t& h23,
                                       uint32_t& l01, uint32_t& l23) {
    __nv_bfloat16 h0 = __float2bfloat16(v.x), h1 = __float2bfloat16(v.y);
    __nv_bfloat16 h2 = __float2bfloat16(v.z), h3 = __float2bfloat16(v.w);
    float l0 = v.x - __bfloat162float(h0), l1 = v.y - __bfloat162float(h1);
    float l2 = v.z - __bfloat162float(h2), l3 = v.w - __bfloat162float(h3);
    __nv_bfloat162 hh0 = __nv_bfloat162(h0, h1), hh1 = __nv_bfloat162(h2, h3);
    h01 = *reinterpret_cast<uint32_t*>(&hh0);
    h23 = *reinterpret_cast<uint32_t*>(&hh1);
    l01 = pack_bf2(l0, l1);
    l23 = pack_bf2(l2, l3);
}

// ---------------------------------------------------------------------------
// SMEM: 2 stages x 4 slabs (AHI, ALO, BHI, BLO), each slab 128 rows x 128B,
// XOR-swizzled 16B chunks. C overlay (float[128][132]) reuses the region.
#define SLAB 16384
#define OFF_AHI 0
#define OFF_ALO SLAB
#define OFF_BHI (2 * SLAB)
#define OFF_BLO (3 * SLAB)
#define STAGE (4 * SLAB)
#define OFF_BIAS (2 * STAGE)
#define SMEM_BYTES (OFF_BIAS + 640)
#define CSTRIDE 132
#define SWZ(row, chunk) ((uint32_t)(row) * 128 + ((uint32_t)((chunk) ^ ((row) & 7)) << 4))

// ---------------------------------------------------------------------------
// GEMM: tile 128x128, K-slab 64, 3-pass bf16 split, 256 thr (8 warps 4x2),
// 2-stage cp.async pipeline.
// MODE: 0 A = pre-split bf16 (lda=128), K=128
//       2 upd: K=256; slabs 0-1 pre-split h, slabs 2-3 fp32 agg (reg split)
// EPI : 0 store fp32 (RELU opt) | 1 store split | 2 h+=relu + split + zero agg
//       3 msg RED scatter | 4 store fp32 + split
template<int MODE, int EPI, bool RELU>
__global__ __launch_bounds__(256)
void mmagemm(const __nv_bfloat16* __restrict__ Ahi, const __nv_bfloat16* __restrict__ Alo,
             const float* __restrict__ Af2,
             const __nv_bfloat16* __restrict__ Bhi, const __nv_bfloat16* __restrict__ Blo,
             const float* __restrict__ bias,
             float* __restrict__ Cout, __nv_bfloat16* __restrict__ OutHi,
             __nv_bfloat16* __restrict__ OutLo,
             const int* __restrict__ src, const int* __restrict__ dst,
             const float* __restrict__ P1, const float* __restrict__ P2,
             float* __restrict__ AGGZ,
             int M, int K)
{
    extern __shared__ char smem[];
    const uint32_t sb = smem_to_u32(smem);
    const int t = threadIdx.x;
    const int lane = t & 31;
    const int wid = t >> 5;
    const int wm = wid & 3;
    const int wn = wid >> 2;
    float* sBias = reinterpret_cast<float*>(smem + OFF_BIAS);
    if (t < 128) sBias[t] = bias[t];

    const int m0 = blockIdx.x * 128;
    const int nslabs = K >> 6;

    float acc[2][8][4];
#pragma unroll
    for (int i = 0; i < 2; ++i)
#pragma unroll
        for (int j = 0; j < 8; ++j)
#pragma unroll
            for (int r = 0; r < 4; ++r) acc[i][j][r] = 0.f;

    // ---- fill lambda ----
    auto issue_fill = [&](int s) {
        const int kb = s << 6;
        const uint32_t buf = sb + (uint32_t)(s & 1) * STAGE;
        if (MODE == 2 && s >= 2) {
            // A from fp32 agg: synchronous register split
#pragma unroll
            for (int i = 0; i < 4; ++i) {
                int id = t + i * 256;
                int row = id >> 3;
                int c = id & 7;
                int m = m0 + row;
                int mc = m < M ? m : M - 1;
                const float* g = &Af2[(size_t)mc * 128 + (kb - 128) + c * 8];
                float4 v0 = *reinterpret_cast<const float4*>(g);
                float4 v1 = *reinterpret_cast<const float4*>(g + 4);
                uint32_t h01, h23, l01, l23, h45, h67, l45, l67;
                split4(v0, h01, h23, l01, l23);
                split4(v1, h45, h67, l45, l67);
                uint32_t off = SWZ(row, c);
                *reinterpret_cast<uint4*>(smem + (s & 1) * STAGE + OFF_AHI + off) =
                    make_uint4(h01, h23, h45, h67);
                *reinterpret_cast<uint4*>(smem + (s & 1) * STAGE + OFF_ALO + off) =
                    make_uint4(l01, l23, l45, l67);
            }
#pragma unroll
            for (int i = 0; i < 4; ++i) {
                int id = t + i * 256;
                int row = id >> 3;
                int c = id & 7;
                uint32_t off = SWZ(row, c);
                cpa16(buf + OFF_BHI + off, Bhi + (size_t)row * K + kb + c * 8);
                cpa16(buf + OFF_BLO + off, Blo + (size_t)row * K + kb + c * 8);
            }
        } else {
#pragma unroll
            for (int i = 0; i < 4; ++i) {
                int id = t + i * 256;
                int row = id >> 3;
                int c = id & 7;
                int m = m0 + row;
                int mc = m < M ? m : M - 1;
                uint32_t off = SWZ(row, c);
                cpa16(buf + OFF_AHI + off, Ahi + (size_t)mc * 128 + kb + c * 8);
                cpa16(buf + OFF_ALO + off, Alo + (size_t)mc * 128 + kb + c * 8);
                cpa16(buf + OFF_BHI + off, Bhi + (size_t)row * K + kb + c * 8);
                cpa16(buf + OFF_BLO + off, Blo + (size_t)row * K + kb + c * 8);
            }
        }
        CP_COMMIT();
    };

    issue_fill(0);
    for (int s = 0; s < nslabs; ++s) {
        if (s + 1 < nslabs) { issue_fill(s + 1); CP_WAIT1(); }
        else                { CP_WAIT0(); }
        __syncthreads();
        const uint32_t buf = sb + (uint32_t)(s & 1) * STAGE;
#pragma unroll
        for (int ks = 0; ks < 4; ++ks) {
            uint32_t ahi[2][4], alo[2][4];
            uint32_t kcol = ks * 16 + (lane >> 4) * 8;
            uint32_t arow = wm * 32 + (lane & 15);
#pragma unroll
            for (int i = 0; i < 2; ++i) {
                uint32_t r = arow + i * 16;
                uint32_t off = SWZ(r, kcol >> 3);
                ldmx4(ahi[i][0], ahi[i][1], ahi[i][2], ahi[i][3], buf + OFF_AHI + off);
                ldmx4(alo[i][0], alo[i][1], alo[i][2], alo[i][3], buf + OFF_ALO + off);
            }
            uint32_t nr = wn * 64 + (lane & 7) + (lane >> 4) * 8;
            uint32_t koff = ks * 16 + ((lane >> 3) & 1) * 8;
#pragma unroll
            for (int j2 = 0; j2 < 4; ++j2) {
                uint32_t r = nr + j2 * 16;
                uint32_t off = SWZ(r, koff >> 3);
                uint32_t bh[4], bl[4];
                ldmx4(bh[0], bh[1], bh[2], bh[3], buf + OFF_BHI + off);
                ldmx4(bl[0], bl[1], bl[2], bl[3], buf + OFF_BLO + off);
#pragma unroll
                for (int i = 0; i < 2; ++i) {
#pragma unroll
                    for (int jj = 0; jj < 2; ++jj) {
                        float* c = acc[i][j2 * 2 + jj];
                        mma_bf16(c[0], c[1], c[2], c[3],
                                 ahi[i][0], ahi[i][1], ahi[i][2], ahi[i][3],
                                 bh[jj * 2], bh[jj * 2 + 1]);
                        mma_bf16(c[0], c[1], c[2], c[3],
                                 alo[i][0], alo[i][1], alo[i][2], alo[i][3],
                                 bh[jj * 2], bh[jj * 2 + 1]);
                        mma_bf16(c[0], c[1], c[2], c[3],
                                 ahi[i][0], ahi[i][1], ahi[i][2], ahi[i][3],
                                 bl[jj * 2], bl[jj * 2 + 1]);
                    }
                }
            }
        }
        __syncthreads();
    }

    // ---- stage C through smem ----
    float* Cs = reinterpret_cast<float*>(smem);
#pragma unroll
    for (int i = 0; i < 2; ++i)
#pragma unroll
        for (int jn = 0; jn < 8; ++jn)
#pragma unroll
            for (int r = 0; r < 4; ++r) {
                int row = wm * 32 + i * 16 + (lane >> 2) + (r >= 2 ? 8 : 0);
                int col = wn * 64 + jn * 8 + (lane & 3) * 2 + (r & 1);
                Cs[row * CSTRIDE + col] = acc[i][jn][r];
            }
    __syncthreads();

    // ---- epilogue: thread t owns row t>>1, cols (t&1)*64 .. +63 ----
    {
        const int row = t >> 1;
        const int cb = (t & 1) * 64;
        const int m = m0 + row;
        if (m < M) {
            const float* crow = &Cs[row * CSTRIDE + cb];
            int sI = 0, dI = 0;
            if (EPI == 3) { sI = __ldg(&src[m]); dI = __ldg(&dst[m]); }
#pragma unroll
            for (int q = 0; q < 16; ++q) {
                float v0 = crow[q*4+0] + sBias[cb + q*4+0];
                float v1 = crow[q*4+1] + sBias[cb + q*4+1];
                float v2 = crow[q*4+2] + sBias[cb + q*4+2];
                float v3 = crow[q*4+3] + sBias[cb + q*4+3];
                if (EPI == 0 || EPI == 4) {
                    if (RELU) { v0 = fmaxf(v0,0.f); v1 = fmaxf(v1,0.f);
                                v2 = fmaxf(v2,0.f); v3 = fmaxf(v3,0.f); }
                    reinterpret_cast<float4*>(&Cout[(size_t)m * 128 + cb])[q] =
                        make_float4(v0, v1, v2, v3);
                    if (EPI == 4) {
                        uint32_t h01, h23, l01, l23;
                        split4(make_float4(v0, v1, v2, v3), h01, h23, l01, l23);
                        reinterpret_cast<uint2*>(OutHi + (size_t)m * 128 + cb)[q] =
                            make_uint2(h01, h23);
                        reinterpret_cast<uint2*>(OutLo + (size_t)m * 128 + cb)[q] =
                            make_uint2(l01, l23);
                    }
                } else if (EPI == 1) {
                    uint32_t h01, h23, l01, l23;
                    split4(make_float4(v0, v1, v2, v3), h01, h23, l01, l23);
                    reinterpret_cast<uint2*>(OutHi + (size_t)m * 128 + cb)[q] =
                        make_uint2(h01, h23);
                    reinterpret_cast<uint2*>(OutLo + (size_t)m * 128 + cb)[q] =
                        make_uint2(l01, l23);
                } else if (EPI == 2) {
                    float* cp = &Cout[(size_t)m * 128 + cb];
                    float4 o = reinterpret_cast<float4*>(cp)[q];
                    o.x += fmaxf(v0, 0.f); o.y += fmaxf(v1, 0.f);
                    o.z += fmaxf(v2, 0.f); o.w += fmaxf(v3, 0.f);
                    reinterpret_cast<float4*>(cp)[q] = o;
                    uint32_t h01, h23, l01, l23;
                    split4(o, h01, h23, l01, l23);
                    reinterpret_cast<uint2*>(OutHi + (size_t)m * 128 + cb)[q] =
                        make_uint2(h01, h23);
                    reinterpret_cast<uint2*>(OutLo + (size_t)m * 128 + cb)[q] =
                        make_uint2(l01, l23);
                    reinterpret_cast<float4*>(&AGGZ[(size_t)m * 128 + cb])[q] =
                        make_float4(0.f, 0.f, 0.f, 0.f);
                } else {  // EPI 3
                    const float4 a = __ldg(&reinterpret_cast<const float4*>(
                                               &P1[(size_t)sI * 128 + cb])[q]);
                    const float4 b = __ldg(&reinterpret_cast<const float4*>(
                                               &P2[(size_t)dI * 128 + cb])[q]);
                    float x0 = fmaxf(v0 + a.x + b.x, 0.f);
                    float x1 = fmaxf(v1 + a.y + b.y, 0.f);
                    float x2 = fmaxf(v2 + a.z + b.z, 0.f);
                    float x3 = fmaxf(v3 + a.w + b.w, 0.f);
                    red_add_v4(&AGGZ[(size_t)dI * 128 + cb + q * 4], x0, x1, x2, x3);
                }
            }
        }
    }
}

// ---------------------------------------------------------------------------
struct PtrTab { const float* p[W128_CNT]; };

__global__ void prep_w128(PtrTab tab, __nv_bfloat16* __restrict__ hi, __nv_bfloat16* __restrict__ lo) {
    int mat = blockIdx.y;
    int i = blockIdx.x * 256 + threadIdx.x;
    if (i >= 16384) return;
    int n = i >> 7, k = i & 127;
    float w = tab.p[mat][k * 128 + n];
    __nv_bfloat16 h = __float2bfloat16(w);
    hi[(size_t)mat * 16384 + i] = h;
    lo[(size_t)mat * 16384 + i] = __float2bfloat16(w - __bfloat162float(h));
}
__global__ void prep_w256(const float* __restrict__ W, __nv_bfloat16* __restrict__ hi,
                          __nv_bfloat16* __restrict__ lo) {
    int mat = blockIdx.y;
    int i = blockIdx.x * 256 + threadIdx.x;
    if (i >= 32768) return;
    int n = i >> 8, k = i & 255;
    float w = W[(size_t)mat * 256 * 128 + k * 128 + n];
    __nv_bfloat16 h = __float2bfloat16(w);
    hi[(size_t)(WUPD_OFF + mat * 32768) + i] = h;
    lo[(size_t)(WUPD_OFF + mat * 32768) + i] = __float2bfloat16(w - __bfloat162float(h));
}

__global__ void zero_kernel(float* __restrict__ p, int n4) {
    int i = blockIdx.x * blockDim.x + threadIdx.x;
    if (i < n4) reinterpret_cast<float4*>(p)[i] = make_float4(0.f, 0.f, 0.f, 0.f);
}

// batched tiny-K first linear + relu, writes pre-split bf16 hi/lo
__global__ void mlp1_kernel(const float* __restrict__ X, const float* __restrict__ W,
                            const float* __restrict__ b,
                            __nv_bfloat16* __restrict__ outHi, __nv_bfloat16* __restrict__ outLo,
                            int K, int M)
{
    __shared__ float Ws[10 * 128];
    __shared__ float Xs[32 * 10];
    __shared__ float bs[128];
    int t = threadIdx.x;  // 128
    for (int i = t; i < K * 128; i += 128) Ws[i] = W[i];
    bs[t] = b[t];
    int r0 = blockIdx.x * 32;
    int nrow = min(32, M - r0);
    for (int i = t; i < nrow * K; i += 128) Xs[i] = X[(size_t)r0 * K + i];
    __syncthreads();
    for (int r = 0; r < nrow; ++r) {
        float acc = bs[t];
        for (int k = 0; k < K; ++k) acc += Xs[r * K + k] * Ws[k * 128 + t];
        acc = fmaxf(acc, 0.f);
        __nv_bfloat16 hv = __float2bfloat16(acc);
        outHi[(size_t)(r0 + r) * 128 + t] = hv;
        outLo[(size_t)(r0 + r) * 128 + t] = __float2bfloat16(acc - __bfloat162float(hv));
    }
}

// fused decoder tail
__global__ void dec2_kernel(const float* __restrict__ f1, const float* __restrict__ W2,
                            const float* __restrict__ b2, const float* __restrict__ W3,
                            const float* __restrict__ b3, const float* __restrict__ bc_disp,
                            const float* __restrict__ bc_rot, const float* __restrict__ face_mask,
                            float* __restrict__ out, int N)
{
    __shared__ float W2s[128 * 64];
    __shared__ float W3s[64 * 15];
    __shared__ float b2s[64], b3s[16];
    __shared__ float f1s[2][128];
    __shared__ float f2s[2][64];

    int t = threadIdx.x;
    for (int i = t; i < 128 * 64; i += 128) W2s[i] = W2[i];
    for (int i = t; i < 64 * 15;  i += 128) W3s[i] = W3[i];
    if (t < 64) b2s[t] = b2[t];
    if (t < 15) b3s[t] = b3[t];
    __syncthreads();

    int base = blockIdx.x * 64;
    for (int it = 0; it < 32; ++it) {
        int n0 = base + it * 2;
#pragma unroll
        for (int r = 0; r < 2; ++r) {
            int n = n0 + r;
            f1s[r][t] = (n < N) ? f1[(size_t)n * 128 + t] : 0.f;
        }
        __syncthreads();
        {
            int rn = t >> 6, j = t & 63;
            float acc = b2s[j];
#pragma unroll 8
            for (int k = 0; k < 128; ++k) acc += f1s[rn][k] * W2s[k * 64 + j];
            f2s[rn][j] = fmaxf(acc, 0.f);
        }
        __syncthreads();
        if (t < 30) {
            int rr = t / 15, c = t % 15;
            int n = n0 + rr;
            if (n < N) {
                float acc = b3s[c];
#pragma unroll 8
                for (int k = 0; k < 64; ++k) acc += f2s[rr][k] * W3s[k * 15 + c];
                float mask;
                if (c < 2)       mask = 1.f - bc_disp[n];
                else if (c == 2) mask = 1.f - bc_rot[n];
                else             mask = face_mask[(size_t)n * 4 + (c - 3) / 3];
                out[(size_t)n * 15 + c] = acc * mask;
            }
        }
        __syncthreads();
    }
}

// ---------------------------------------------------------------------------
extern "C" void kernel_launch(void* const* d_in, const int* in_sizes, int n_in,
                              void* d_out, int out_size)
{
    const float* x         = (const float*)d_in[0];
    const float* edge_attr = (const float*)d_in[1];
    const int*   edge_idx  = (const int*)  d_in[2];
    const float* bc_disp   = (const float*)d_in[3];
    const float* bc_rot    = (const float*)d_in[4];
    const float* face_mask = (const float*)d_in[5];
    const float* enc_n_W1  = (const float*)d_in[6];
    const float* enc_n_b1  = (const float*)d_in[7];
    const float* enc_n_W2  = (const float*)d_in[8];
    const float* enc_n_b2  = (const float*)d_in[9];
    const float* enc_e_W1  = (const float*)d_in[10];
    const float* enc_e_b1  = (const float*)d_in[11];
    const float* enc_e_W2  = (const float*)d_in[12];
    const float* enc_e_b2  = (const float*)d_in[13];
    const float* msg_W     = (const float*)d_in[14];
    const float* msg_b     = (const float*)d_in[15];
    const float* upd_W     = (const float*)d_in[16];
    const float* upd_b     = (const float*)d_in[17];
    const float* dec_W1    = (const float*)d_in[18];
    const float* dec_b1    = (const float*)d_in[19];
    const float* dec_W2    = (const float*)d_in[20];
    const float* dec_b2    = (const float*)d_in[21];
    const float* dec_W3    = (const float*)d_in[22];
    const float* dec_b3    = (const float*)d_in[23];

    const int N = in_sizes[0] / 9;
    const int E = in_sizes[1] / 10;
    const int* src = edge_idx;
    const int* dst = edge_idx + E;

    float *h, *agg, *f1, *p1, *p2, *zb;
    __nv_bfloat16 *hhi, *hlo, *ehi, *elo, *thi, *tlo, *whi, *wlo;
    cudaGetSymbolAddress((void**)&h,   g_h);
    cudaGetSymbolAddress((void**)&agg, g_agg);
    cudaGetSymbolAddress((void**)&f1,  g_f1);
    cudaGetSymbolAddress((void**)&p1,  g_p1);
    cudaGetSymbolAddress((void**)&p2,  g_p2);
    cudaGetSymbolAddress((void**)&zb,  g_zbias);
    cudaGetSymbolAddress((void**)&hhi, g_hhi);
    cudaGetSymbolAddress((void**)&hlo, g_hlo);
    cudaGetSymbolAddress((void**)&ehi, g_ehi);
    cudaGetSymbolAddress((void**)&elo, g_elo);
    cudaGetSymbolAddress((void**)&thi, g_thi);
    cudaGetSymbolAddress((void**)&tlo, g_tlo);
    cudaGetSymbolAddress((void**)&whi, g_whi);
    cudaGetSymbolAddress((void**)&wlo, g_wlo);

    cudaFuncSetAttribute((const void*)mmagemm<0,4,false>, cudaFuncAttributeMaxDynamicSharedMemorySize, SMEM_BYTES);
    cudaFuncSetAttribute((const void*)mmagemm<0,1,false>, cudaFuncAttributeMaxDynamicSharedMemorySize, SMEM_BYTES);
    cudaFuncSetAttribute((const void*)mmagemm<0,0,false>, cudaFuncAttributeMaxDynamicSharedMemorySize, SMEM_BYTES);
    cudaFuncSetAttribute((const void*)mmagemm<0,0,true>,  cudaFuncAttributeMaxDynamicSharedMemorySize, SMEM_BYTES);
    cudaFuncSetAttribute((const void*)mmagemm<0,3,true>,  cudaFuncAttributeMaxDynamicSharedMemorySize, SMEM_BYTES);
    cudaFuncSetAttribute((const void*)mmagemm<2,2,true>,  cudaFuncAttributeMaxDynamicSharedMemorySize, SMEM_BYTES);

    // ---- weight prep ----
    PtrTab tab;
    tab.p[0] = enc_n_W2;
    tab.p[1] = enc_e_W2;
    tab.p[2] = dec_W1;
    for (int l = 0; l < 6; ++l)
        for (int j = 0; j < 3; ++j)
            tab.p[3 + l * 3 + j] = msg_W + (size_t)l * 384 * 128 + (size_t)j * 128 * 128;
    prep_w128<<<dim3(64, W128_CNT), 256>>>(tab, whi, wlo);
    prep_w256<<<dim3(128, 6), 256>>>(upd_W, whi, wlo);

    const int gN = (N + 127) / 128;
    const int gE = (E + 127) / 128;
    auto WH = [&](int j) { return whi + (size_t)j * 16384; };
    auto WL = [&](int j) { return wlo + (size_t)j * 16384; };

    // ---- encoders ----
    mlp1_kernel<<<(N + 31) / 32, 128>>>(x, enc_n_W1, enc_n_b1, thi, tlo, 9, N);
    mmagemm<0,4,false><<<gN, 256, SMEM_BYTES>>>(thi, tlo, nullptr, WH(0), WL(0),
        enc_n_b2, h, hhi, hlo, nullptr, nullptr, nullptr, nullptr, nullptr, N, 128);
    mlp1_kernel<<<(E + 31) / 32, 128>>>(edge_attr, enc_e_W1, enc_e_b1, thi, tlo, 10, E);
    mmagemm<0,1,false><<<gE, 256, SMEM_BYTES>>>(thi, tlo, nullptr, WH(1), WL(1),
        enc_e_b2, nullptr, ehi, elo, nullptr, nullptr, nullptr, nullptr, nullptr, E, 128);

    zero_kernel<<<(N * 128 / 4 + 255) / 256, 256>>>(agg, N * 128 / 4);

    // ---- message-passing layers ----
    for (int l = 0; l < 6; ++l) {
        int j = 3 + l * 3;
        mmagemm<0,0,false><<<gN, 256, SMEM_BYTES>>>(hhi, hlo, nullptr, WH(j), WL(j),
            zb, p1, nullptr, nullptr, nullptr, nullptr, nullptr, nullptr, nullptr, N, 128);
        mmagemm<0,0,false><<<gN, 256, SMEM_BYTES>>>(hhi, hlo, nullptr, WH(j+1), WL(j+1),
            zb, p2, nullptr, nullptr, nullptr, nullptr, nullptr, nullptr, nullptr, N, 128);
        mmagemm<0,3,true><<<gE, 256, SMEM_BYTES>>>(ehi, elo, nullptr, WH(j+2), WL(j+2),
            msg_b + l * 128, nullptr, nullptr, nullptr, src, dst, p1, p2, agg, E, 128);
        mmagemm<2,2,true><<<gN, 256, SMEM_BYTES>>>(hhi, hlo, agg,
            whi + WUPD_OFF + (size_t)l * 32768, wlo + WUPD_OFF + (size_t)l * 32768,
            upd_b + l * 128, h, hhi, hlo, nullptr, nullptr, nullptr, nullptr, agg, N, 256);
    }

    // ---- decoder ----
    mmagemm<0,0,true><<<gN, 256, SMEM_BYTES>>>(hhi, hlo, nullptr, WH(2), WL(2),
        dec_b1, f1, nullptr, nullptr, nullptr, nullptr, nullptr, nullptr, nullptr, N, 128);
    dec2_kernel<<<(N + 63) / 64, 128>>>(f1, dec_W2, dec_b2, dec_W3, dec_b3,
                                        bc_disp, bc_rot, face_mask, (float*)d_out, N);
}

// round 7
// speedup vs baseline: 2.3015x; 1.0929x over previous
#include <cuda_runtime.h>
#include <cuda_bf16.h>
#include <cstdint>

// ===========================================================================
// PIGNN forward — mma.sync bf16 hi/lo split GEMMs.
// K-slab 32, 3-stage cp.async pipeline, 2 CTAs/SM (96KB smem, <=128 regs).
//   msg_in @ mW == h[src]@mW1 + h[dst]@mW2 + e@mW3
// ===========================================================================

#define NN_MAX 100000
#define NE_MAX 600000

__device__ float g_h   [(size_t)NN_MAX * 128];
__device__ float g_agg [(size_t)NN_MAX * 128];
__device__ float g_f1  [(size_t)NN_MAX * 128];
__device__ float g_p1  [(size_t)NN_MAX * 128];
__device__ float g_p2  [(size_t)NN_MAX * 128];
__device__ __nv_bfloat16 g_hhi[(size_t)NN_MAX * 128];
__device__ __nv_bfloat16 g_hlo[(size_t)NN_MAX * 128];
__device__ __nv_bfloat16 g_ehi[(size_t)NE_MAX * 128];
__device__ __nv_bfloat16 g_elo[(size_t)NE_MAX * 128];
__device__ __nv_bfloat16 g_thi[(size_t)NE_MAX * 128];
__device__ __nv_bfloat16 g_tlo[(size_t)NE_MAX * 128];
#define W128_CNT 21
#define WUPD_OFF (W128_CNT * 16384)
#define WTOT (WUPD_OFF + 6 * 32768)
__device__ __nv_bfloat16 g_whi[WTOT];
__device__ __nv_bfloat16 g_wlo[WTOT];
__device__ float g_zbias[128];   // zero-initialized, never written

// ---------------------------------------------------------------------------
__device__ __forceinline__ uint32_t smem_to_u32(const void* p) {
    uint32_t a;
    asm("{ .reg .u64 t; cvta.to.shared.u64 t, %1; cvt.u32.u64 %0, t; }" : "=r"(a) : "l"(p));
    return a;
}
__device__ __forceinline__ void ldmx4(uint32_t& r0, uint32_t& r1, uint32_t& r2, uint32_t& r3,
                                      uint32_t addr) {
    asm volatile("ldmatrix.sync.aligned.m8n8.x4.shared.b16 {%0,%1,%2,%3}, [%4];"
                 : "=r"(r0), "=r"(r1), "=r"(r2), "=r"(r3) : "r"(addr));
}
__device__ __forceinline__ void mma_bf16(float& c0, float& c1, float& c2, float& c3,
                                         uint32_t a0, uint32_t a1, uint32_t a2, uint32_t a3,
                                         uint32_t b0, uint32_t b1) {
    asm volatile("mma.sync.aligned.m16n8k16.row.col.f32.bf16.bf16.f32 "
                 "{%0,%1,%2,%3}, {%4,%5,%6,%7}, {%8,%9}, {%0,%1,%2,%3};"
                 : "+f"(c0), "+f"(c1), "+f"(c2), "+f"(c3)
                 : "r"(a0), "r"(a1), "r"(a2), "r"(a3), "r"(b0), "r"(b1));
}
__device__ __forceinline__ void cpa16(uint32_t saddr, const void* g) {
    asm volatile("cp.async.cg.shared.global [%0], [%1], 16;" :: "r"(saddr), "l"(g));
}
#define CP_COMMIT() asm volatile("cp.async.commit_group;" ::: "memory")
#define CP_WAIT2()  asm volatile("cp.async.wait_group 2;" ::: "memory")
#define CP_WAIT1()  asm volatile("cp.async.wait_group 1;" ::: "memory")
#define CP_WAIT0()  asm volatile("cp.async.wait_group 0;" ::: "memory")
__device__ __forceinline__ void red_add_v4(float* addr, float a, float b, float c, float d) {
    asm volatile("red.global.add.v4.f32 [%0], {%1,%2,%3,%4};"
                 :: "l"(addr), "f"(a), "f"(b), "f"(c), "f"(d) : "memory");
}
__device__ __forceinline__ uint32_t pack_bf2(float a, float b) {
    __nv_bfloat162 v = __floats2bfloat162_rn(a, b);
    return *reinterpret_cast<uint32_t*>(&v);
}
__device__ __forceinline__ void split4(const float4 v, uint32_t& h01, uint32_t& h23,
                                       uint32_t& l01, uint32_t& l23) {
    __nv_bfloat16 h0 = __float2bfloat16(v.x), h1 = __float2bfloat16(v.y);
    __nv_bfloat16 h2 = __float2bfloat16(v.z), h3 = __float2bfloat16(v.w);
    float l0 = v.x - __bfloat162float(h0), l1 = v.y - __bfloat162float(h1);
    float l2 = v.z - __bfloat162float(h2), l3 = v.w - __bfloat162float(h3);
    __nv_bfloat162 hh0 = __nv_bfloat162(h0, h1), hh1 = __nv_bfloat162(h2, h3);
    h01 = *reinterpret_cast<uint32_t*>(&hh0);
    h23 = *reinterpret_cast<uint32_t*>(&hh1);
    l01 = pack_bf2(l0, l1);
    l23 = pack_bf2(l2, l3);
}

// ---------------------------------------------------------------------------
// SMEM: 3 stages x (AHI 8K | ALO 8K | BHI 8K | BLO 8K) = 96KB, + bias.
// Slab = 128 rows x 32 bf16 (64B rows), 16B chunks 0..3, swizzled.
#define OFF_AHI 0
#define OFF_ALO 8192
#define OFF_BHI 16384
#define OFF_BLO 24576
#define STAGE 32768
#define OFF_BIAS (3 * STAGE)
#define SMEM_BYTES (OFF_BIAS + 640)
#define CSTRIDE 132
#define SWZ(row, chunk) ((uint32_t)(row) * 64 + ((uint32_t)((chunk) ^ (((row) >> 1) & 3)) << 4))

// ---------------------------------------------------------------------------
// GEMM: tile 128x128, K-slab 32, 3-pass bf16 split, 256 thr (8 warps 4x2),
// 3-stage cp.async pipeline, 2 CTAs/SM.
// MODE: 0 A = pre-split bf16 (lda=128) | 2 upd: slabs 0-3 pre-split h, 4-7 fp32 agg
// EPI : 0 store fp32 (RELU opt) | 1 store split | 2 h+=relu + split + zero agg
//       3 msg RED scatter | 4 store fp32 + split
// DUAL: grid.x = 2*half; upper half uses Bhi2/Blo2 -> Cout2.
template<int MODE, int EPI, bool RELU, bool DUAL>
__global__ __launch_bounds__(256, 2)
void mmagemm(const __nv_bfloat16* __restrict__ Ahi_, const __nv_bfloat16* __restrict__ Alo_,
             const float* __restrict__ Af2,
             const __nv_bfloat16* __restrict__ Bhi_, const __nv_bfloat16* __restrict__ Blo_,
             const __nv_bfloat16* __restrict__ Bhi2, const __nv_bfloat16* __restrict__ Blo2,
             const float* __restrict__ bias,
             float* __restrict__ Cout_, float* __restrict__ Cout2,
             __nv_bfloat16* __restrict__ OutHi, __nv_bfloat16* __restrict__ OutLo,
             const int* __restrict__ src, const int* __restrict__ dst,
             const float* __restrict__ P1, const float* __restrict__ P2,
             float* __restrict__ AGGZ,
             int M, int K)
{
    extern __shared__ char smem[];
    const uint32_t sb = smem_to_u32(smem);
    const int t = threadIdx.x;
    const int lane = t & 31;
    const int wid = t >> 5;
    const int wm = wid & 3;
    const int wn = wid >> 2;

    const __nv_bfloat16* Ahi = Ahi_;
    const __nv_bfloat16* Alo = Alo_;
    const __nv_bfloat16* Bhi = Bhi_;
    const __nv_bfloat16* Blo = Blo_;
    float* Cout = Cout_;
    int bid = blockIdx.x;
    if (DUAL) {
        int half = gridDim.x >> 1;
        if (bid >= half) { bid -= half; Bhi = Bhi2; Blo = Blo2; Cout = Cout2; }
    }
    const int m0 = bid * 128;

    float* sBias = reinterpret_cast<float*>(smem + OFF_BIAS);
    if (t < 128) sBias[t] = bias[t];

    const int nslabs = K >> 5;

    float acc[2][8][4];
#pragma unroll
    for (int i = 0; i < 2; ++i)
#pragma unroll
        for (int j = 0; j < 8; ++j)
#pragma unroll
            for (int r = 0; r < 4; ++r) acc[i][j][r] = 0.f;

    auto issue_fill = [&](int s) {
        const int kb = s << 5;
        const uint32_t st = (uint32_t)(s % 3) * STAGE;
        const uint32_t buf = sb + st;
        if (MODE == 2 && s >= 4) {
            // A from fp32 agg: synchronous register split (2 chunks/thread)
#pragma unroll
            for (int i = 0; i < 2; ++i) {
                int id = t + i * 256;
                int row = id >> 2;
                int c = id & 3;
                int m = m0 + row;
                int mc = m < M ? m : M - 1;
                const float* g = &Af2[(size_t)mc * 128 + (kb - 128) + c * 8];
                float4 v0 = *reinterpret_cast<const float4*>(g);
                float4 v1 = *reinterpret_cast<const float4*>(g + 4);
                uint32_t h01, h23, l01, l23, h45, h67, l45, l67;
                split4(v0, h01, h23, l01, l23);
                split4(v1, h45, h67, l45, l67);
                uint32_t off = SWZ(row, c);
                *reinterpret_cast<uint4*>(smem + st + OFF_AHI + off) =
                    make_uint4(h01, h23, h45, h67);
                *reinterpret_cast<uint4*>(smem + st + OFF_ALO + off) =
                    make_uint4(l01, l23, l45, l67);
            }
#pragma unroll
            for (int i = 0; i < 2; ++i) {
                int id = t + i * 256;
                int row = id >> 2;
                int c = id & 3;
                uint32_t off = SWZ(row, c);
                cpa16(buf + OFF_BHI + off, Bhi + (size_t)row * K + kb + c * 8);
                cpa16(buf + OFF_BLO + off, Blo + (size_t)row * K + kb + c * 8);
            }
        } else {
#pragma unroll
            for (int i = 0; i < 2; ++i) {
                int id = t + i * 256;
                int row = id >> 2;
                int c = id & 3;
                int m = m0 + row;
                int mc = m < M ? m : M - 1;
                uint32_t off = SWZ(row, c);
                cpa16(buf + OFF_AHI + off, Ahi + (size_t)mc * 128 + kb + c * 8);
                cpa16(buf + OFF_ALO + off, Alo + (size_t)mc * 128 + kb + c * 8);
                cpa16(buf + OFF_BHI + off, Bhi + (size_t)row * K + kb + c * 8);
                cpa16(buf + OFF_BLO + off, Blo + (size_t)row * K + kb + c * 8);
            }
        }
        CP_COMMIT();
    };

    issue_fill(0);
    issue_fill(1);
    for (int s = 0; s < nslabs; ++s) {
        __syncthreads();   // all warps done reading stage (s+2)%3 (from slab s-1 epoch)
        if (s + 2 < nslabs) { issue_fill(s + 2); CP_WAIT2(); }
        else if (s + 1 < nslabs) { CP_WAIT1(); }
        else { CP_WAIT0(); }
        __syncthreads();
        const uint32_t buf = sb + (uint32_t)(s % 3) * STAGE;
#pragma unroll
        for (int ks = 0; ks < 2; ++ks) {
            uint32_t ahi[2][4], alo[2][4];
            uint32_t ca = ks * 2 + (lane >> 4);      // A chunk index
            uint32_t arow = wm * 32 + (lane & 15);
#pragma unroll
            for (int i = 0; i < 2; ++i) {
                uint32_t r = arow + i * 16;
                uint32_t off = SWZ(r, ca);
                ldmx4(ahi[i][0], ahi[i][1], ahi[i][2], ahi[i][3], buf + OFF_AHI + off);
                ldmx4(alo[i][0], alo[i][1], alo[i][2], alo[i][3], buf + OFF_ALO + off);
            }
            uint32_t nr = wn * 64 + (lane & 7) + (lane >> 4) * 8;
            uint32_t cbk = ks * 2 + ((lane >> 3) & 1);  // B chunk index
#pragma unroll
            for (int j2 = 0; j2 < 4; ++j2) {
                uint32_t r = nr + j2 * 16;
                uint32_t off = SWZ(r, cbk);
                uint32_t bh[4], bl[4];
                ldmx4(bh[0], bh[1], bh[2], bh[3], buf + OFF_BHI + off);
                ldmx4(bl[0], bl[1], bl[2], bl[3], buf + OFF_BLO + off);
#pragma unroll
                for (int i = 0; i < 2; ++i) {
#pragma unroll
                    for (int jj = 0; jj < 2; ++jj) {
                        float* c = acc[i][j2 * 2 + jj];
                        mma_bf16(c[0], c[1], c[2], c[3],
                                 ahi[i][0], ahi[i][1], ahi[i][2], ahi[i][3],
                                 bh[jj * 2], bh[jj * 2 + 1]);
                        mma_bf16(c[0], c[1], c[2], c[3],
                                 alo[i][0], alo[i][1], alo[i][2], alo[i][3],
                                 bh[jj * 2], bh[jj * 2 + 1]);
                        mma_bf16(c[0], c[1], c[2], c[3],
                                 ahi[i][0], ahi[i][1], ahi[i][2], ahi[i][3],
                                 bl[jj * 2], bl[jj * 2 + 1]);
                    }
                }
            }
        }
    }
    __syncthreads();

    // ---- stage C through smem (overlays the stage buffers) ----
    float* Cs = reinterpret_cast<float*>(smem);
#pragma unroll
    for (int i = 0; i < 2; ++i)
#pragma unroll
        for (int jn = 0; jn < 8; ++jn)
#pragma unroll
            for (int r = 0; r < 4; ++r) {
                int row = wm * 32 + i * 16 + (lane >> 2) + (r >= 2 ? 8 : 0);
                int col = wn * 64 + jn * 8 + (lane & 3) * 2 + (r & 1);
                Cs[row * CSTRIDE + col] = acc[i][jn][r];
            }
    __syncthreads();

    // ---- epilogue: thread t owns row t>>1, cols (t&1)*64 .. +63 ----
    {
        const int row = t >> 1;
        const int cb = (t & 1) * 64;
        const int m = m0 + row;
        if (m < M) {
            const float* crow = &Cs[row * CSTRIDE + cb];
            int sI = 0, dI = 0;
            if (EPI == 3) { sI = __ldg(&src[m]); dI = __ldg(&dst[m]); }
#pragma unroll
            for (int q = 0; q < 16; ++q) {
                float v0 = crow[q*4+0] + sBias[cb + q*4+0];
                float v1 = crow[q*4+1] + sBias[cb + q*4+1];
                float v2 = crow[q*4+2] + sBias[cb + q*4+2];
                float v3 = crow[q*4+3] + sBias[cb + q*4+3];
                if (EPI == 0 || EPI == 4) {
                    if (RELU) { v0 = fmaxf(v0,0.f); v1 = fmaxf(v1,0.f);
                                v2 = fmaxf(v2,0.f); v3 = fmaxf(v3,0.f); }
                    reinterpret_cast<float4*>(&Cout[(size_t)m * 128 + cb])[q] =
                        make_float4(v0, v1, v2, v3);
                    if (EPI == 4) {
                        uint32_t h01, h23, l01, l23;
                        split4(make_float4(v0, v1, v2, v3), h01, h23, l01, l23);
                        reinterpret_cast<uint2*>(OutHi + (size_t)m * 128 + cb)[q] =
                            make_uint2(h01, h23);
                        reinterpret_cast<uint2*>(OutLo + (size_t)m * 128 + cb)[q] =
                            make_uint2(l01, l23);
                    }
                } else if (EPI == 1) {
                    uint32_t h01, h23, l01, l23;
                    split4(make_float4(v0, v1, v2, v3), h01, h23, l01, l23);
                    reinterpret_cast<uint2*>(OutHi + (size_t)m * 128 + cb)[q] =
                        make_uint2(h01, h23);
                    reinterpret_cast<uint2*>(OutLo + (size_t)m * 128 + cb)[q] =
                        make_uint2(l01, l23);
                } else if (EPI == 2) {
                    float* cp = &Cout[(size_t)m * 128 + cb];
                    float4 o = reinterpret_cast<float4*>(cp)[q];
                    o.x += fmaxf(v0, 0.f); o.y += fmaxf(v1, 0.f);
                    o.z += fmaxf(v2, 0.f); o.w += fmaxf(v3, 0.f);
                    reinterpret_cast<float4*>(cp)[q] = o;
                    uint32_t h01, h23, l01, l23;
                    split4(o, h01, h23, l01, l23);
                    reinterpret_cast<uint2*>(OutHi + (size_t)m * 128 + cb)[q] =
                        make_uint2(h01, h23);
                    reinterpret_cast<uint2*>(OutLo + (size_t)m * 128 + cb)[q] =
                        make_uint2(l01, l23);
                    reinterpret_cast<float4*>(&AGGZ[(size_t)m * 128 + cb])[q] =
                        make_float4(0.f, 0.f, 0.f, 0.f);
                } else {  // EPI 3
                    const float4 a = __ldg(&reinterpret_cast<const float4*>(
                                               &P1[(size_t)sI * 128 + cb])[q]);
                    const float4 b = __ldg(&reinterpret_cast<const float4*>(
                                               &P2[(size_t)dI * 128 + cb])[q]);
                    float x0 = fmaxf(v0 + a.x + b.x, 0.f);
                    float x1 = fmaxf(v1 + a.y + b.y, 0.f);
                    float x2 = fmaxf(v2 + a.z + b.z, 0.f);
                    float x3 = fmaxf(v3 + a.w + b.w, 0.f);
                    red_add_v4(&AGGZ[(size_t)dI * 128 + cb + q * 4], x0, x1, x2, x3);
                }
            }
        }
    }
}

// ---------------------------------------------------------------------------
struct PtrTab { const float* p[W128_CNT]; };

__global__ void prep_w128(PtrTab tab, __nv_bfloat16* __restrict__ hi, __nv_bfloat16* __restrict__ lo) {
    int mat = blockIdx.y;
    int i = blockIdx.x * 256 + threadIdx.x;
    if (i >= 16384) return;
    int n = i >> 7, k = i & 127;
    float w = tab.p[mat][k * 128 + n];
    __nv_bfloat16 h = __float2bfloat16(w);
    hi[(size_t)mat * 16384 + i] = h;
    lo[(size_t)mat * 16384 + i] = __float2bfloat16(w - __bfloat162float(h));
}
__global__ void prep_w256(const float* __restrict__ W, __nv_bfloat16* __restrict__ hi,
                          __nv_bfloat16* __restrict__ lo) {
    int mat = blockIdx.y;
    int i = blockIdx.x * 256 + threadIdx.x;
    if (i >= 32768) return;
    int n = i >> 8, k = i & 255;
    float w = W[(size_t)mat * 256 * 128 + k * 128 + n];
    __nv_bfloat16 h = __float2bfloat16(w);
    hi[(size_t)(WUPD_OFF + mat * 32768) + i] = h;
    lo[(size_t)(WUPD_OFF + mat * 32768) + i] = __float2bfloat16(w - __bfloat162float(h));
}

__global__ void zero_kernel(float* __restrict__ p, int n4) {
    int i = blockIdx.x * blockDim.x + threadIdx.x;
    if (i < n4) reinterpret_cast<float4*>(p)[i] = make_float4(0.f, 0.f, 0.f, 0.f);
}

// batched tiny-K first linear + relu, writes pre-split bf16 hi/lo
__global__ void mlp1_kernel(const float* __restrict__ X, const float* __restrict__ W,
                            const float* __restrict__ b,
                            __nv_bfloat16* __restrict__ outHi, __nv_bfloat16* __restrict__ outLo,
                            int K, int M)
{
    __shared__ float Ws[10 * 128];
    __shared__ float Xs[32 * 10];
    __shared__ float bs[128];
    int t = threadIdx.x;  // 128
    for (int i = t; i < K * 128; i += 128) Ws[i] = W[i];
    bs[t] = b[t];
    int r0 = blockIdx.x * 32;
    int nrow = min(32, M - r0);
    for (int i = t; i < nrow * K; i += 128) Xs[i] = X[(size_t)r0 * K + i];
    __syncthreads();
    for (int r = 0; r < nrow; ++r) {
        float acc = bs[t];
        for (int k = 0; k < K; ++k) acc += Xs[r * K + k] * Ws[k * 128 + t];
        acc = fmaxf(acc, 0.f);
        __nv_bfloat16 hv = __float2bfloat16(acc);
        outHi[(size_t)(r0 + r) * 128 + t] = hv;
        outLo[(size_t)(r0 + r) * 128 + t] = __float2bfloat16(acc - __bfloat162float(hv));
    }
}

// fused decoder tail
__global__ void dec2_kernel(const float* __restrict__ f1, const float* __restrict__ W2,
                            const float* __restrict__ b2, const float* __restrict__ W3,
                            const float* __restrict__ b3, const float* __restrict__ bc_disp,
                            const float* __restrict__ bc_rot, const float* __restrict__ face_mask,
                            float* __restrict__ out, int N)
{
    __shared__ float W2s[128 * 64];
    __shared__ float W3s[64 * 15];
    __shared__ float b2s[64], b3s[16];
    __shared__ float f1s[2][128];
    __shared__ float f2s[2][64];

    int t = threadIdx.x;
    for (int i = t; i < 128 * 64; i += 128) W2s[i] = W2[i];
    for (int i = t; i < 64 * 15;  i += 128) W3s[i] = W3[i];
    if (t < 64) b2s[t] = b2[t];
    if (t < 15) b3s[t] = b3[t];
    __syncthreads();

    int base = blockIdx.x * 64;
    for (int it = 0; it < 32; ++it) {
        int n0 = base + it * 2;
#pragma unroll
        for (int r = 0; r < 2; ++r) {
            int n = n0 + r;
            f1s[r][t] = (n < N) ? f1[(size_t)n * 128 + t] : 0.f;
        }
        __syncthreads();
        {
            int rn = t >> 6, j = t & 63;
            float acc = b2s[j];
#pragma unroll 8
            for (int k = 0; k < 128; ++k) acc += f1s[rn][k] * W2s[k * 64 + j];
            f2s[rn][j] = fmaxf(acc, 0.f);
        }
        __syncthreads();
        if (t < 30) {
            int rr = t / 15, c = t % 15;
            int n = n0 + rr;
            if (n < N) {
                float acc = b3s[c];
#pragma unroll 8
                for (int k = 0; k < 64; ++k) acc += f2s[rr][k] * W3s[k * 15 + c];
                float mask;
                if (c < 2)       mask = 1.f - bc_disp[n];
                else if (c == 2) mask = 1.f - bc_rot[n];
                else             mask = face_mask[(size_t)n * 4 + (c - 3) / 3];
                out[(size_t)n * 15 + c] = acc * mask;
            }
        }
        __syncthreads();
    }
}

// ---------------------------------------------------------------------------
extern "C" void kernel_launch(void* const* d_in, const int* in_sizes, int n_in,
                              void* d_out, int out_size)
{
    const float* x         = (const float*)d_in[0];
    const float* edge_attr = (const float*)d_in[1];
    const int*   edge_idx  = (const int*)  d_in[2];
    const float* bc_disp   = (const float*)d_in[3];
    const float* bc_rot    = (const float*)d_in[4];
    const float* face_mask = (const float*)d_in[5];
    const float* enc_n_W1  = (const float*)d_in[6];
    const float* enc_n_b1  = (const float*)d_in[7];
    const float* enc_n_W2  = (const float*)d_in[8];
    const float* enc_n_b2  = (const float*)d_in[9];
    const float* enc_e_W1  = (const float*)d_in[10];
    const float* enc_e_b1  = (const float*)d_in[11];
    const float* enc_e_W2  = (const float*)d_in[12];
    const float* enc_e_b2  = (const float*)d_in[13];
    const float* msg_W     = (const float*)d_in[14];
    const float* msg_b     = (const float*)d_in[15];
    const float* upd_W     = (const float*)d_in[16];
    const float* upd_b     = (const float*)d_in[17];
    const float* dec_W1    = (const float*)d_in[18];
    const float* dec_b1    = (const float*)d_in[19];
    const float* dec_W2    = (const float*)d_in[20];
    const float* dec_b2    = (const float*)d_in[21];
    const float* dec_W3    = (const float*)d_in[22];
    const float* dec_b3    = (const float*)d_in[23];

    const int N = in_sizes[0] / 9;
    const int E = in_sizes[1] / 10;
    const int* src = edge_idx;
    const int* dst = edge_idx + E;

    float *h, *agg, *f1, *p1, *p2, *zb;
    __nv_bfloat16 *hhi, *hlo, *ehi, *elo, *thi, *tlo, *whi, *wlo;
    cudaGetSymbolAddress((void**)&h,   g_h);
    cudaGetSymbolAddress((void**)&agg, g_agg);
    cudaGetSymbolAddress((void**)&f1,  g_f1);
    cudaGetSymbolAddress((void**)&p1,  g_p1);
    cudaGetSymbolAddress((void**)&p2,  g_p2);
    cudaGetSymbolAddress((void**)&zb,  g_zbias);
    cudaGetSymbolAddress((void**)&hhi, g_hhi);
    cudaGetSymbolAddress((void**)&hlo, g_hlo);
    cudaGetSymbolAddress((void**)&ehi, g_ehi);
    cudaGetSymbolAddress((void**)&elo, g_elo);
    cudaGetSymbolAddress((void**)&thi, g_thi);
    cudaGetSymbolAddress((void**)&tlo, g_tlo);
    cudaGetSymbolAddress((void**)&whi, g_whi);
    cudaGetSymbolAddress((void**)&wlo, g_wlo);

    cudaFuncSetAttribute((const void*)mmagemm<0,4,false,false>, cudaFuncAttributeMaxDynamicSharedMemorySize, SMEM_BYTES);
    cudaFuncSetAttribute((const void*)mmagemm<0,1,false,false>, cudaFuncAttributeMaxDynamicSharedMemorySize, SMEM_BYTES);
    cudaFuncSetAttribute((const void*)mmagemm<0,0,false,true>,  cudaFuncAttributeMaxDynamicSharedMemorySize, SMEM_BYTES);
    cudaFuncSetAttribute((const void*)mmagemm<0,0,true,false>,  cudaFuncAttributeMaxDynamicSharedMemorySize, SMEM_BYTES);
    cudaFuncSetAttribute((const void*)mmagemm<0,3,true,false>,  cudaFuncAttributeMaxDynamicSharedMemorySize, SMEM_BYTES);
    cudaFuncSetAttribute((const void*)mmagemm<2,2,true,false>,  cudaFuncAttributeMaxDynamicSharedMemorySize, SMEM_BYTES);

    // ---- weight prep ----
    PtrTab tab;
    tab.p[0] = enc_n_W2;
    tab.p[1] = enc_e_W2;
    tab.p[2] = dec_W1;
    for (int l = 0; l < 6; ++l)
        for (int j = 0; j < 3; ++j)
            tab.p[3 + l * 3 + j] = msg_W + (size_t)l * 384 * 128 + (size_t)j * 128 * 128;
    prep_w128<<<dim3(64, W128_CNT), 256>>>(tab, whi, wlo);
    prep_w256<<<dim3(128, 6), 256>>>(upd_W, whi, wlo);

    const int gN = (N + 127) / 128;
    const int gE = (E + 127) / 128;
    auto WH = [&](int j) { return whi + (size_t)j * 16384; };
    auto WL = [&](int j) { return wlo + (size_t)j * 16384; };

    // ---- encoders ----
    mlp1_kernel<<<(N + 31) / 32, 128>>>(x, enc_n_W1, enc_n_b1, thi, tlo, 9, N);
    mmagemm<0,4,false,false><<<gN, 256, SMEM_BYTES>>>(thi, tlo, nullptr, WH(0), WL(0),
        nullptr, nullptr, enc_n_b2, h, nullptr, hhi, hlo,
        nullptr, nullptr, nullptr, nullptr, nullptr, N, 128);
    mlp1_kernel<<<(E + 31) / 32, 128>>>(edge_attr, enc_e_W1, enc_e_b1, thi, tlo, 10, E);
    mmagemm<0,1,false,false><<<gE, 256, SMEM_BYTES>>>(thi, tlo, nullptr, WH(1), WL(1),
        nullptr, nullptr, enc_e_b2, nullptr, nullptr, ehi, elo,
        nullptr, nullptr, nullptr, nullptr, nullptr, E, 128);

    zero_kernel<<<(N * 128 / 4 + 255) / 256, 256>>>(agg, N * 128 / 4);

    // ---- message-passing layers ----
    for (int l = 0; l < 6; ++l) {
        int j = 3 + l * 3;
        // P1 = h@mW1 and P2 = h@mW2 in one dual launch
        mmagemm<0,0,false,true><<<2 * gN, 256, SMEM_BYTES>>>(hhi, hlo, nullptr,
            WH(j), WL(j), WH(j+1), WL(j+1), zb, p1, p2, nullptr, nullptr,
            nullptr, nullptr, nullptr, nullptr, nullptr, N, 128);
        mmagemm<0,3,true,false><<<gE, 256, SMEM_BYTES>>>(ehi, elo, nullptr,
            WH(j+2), WL(j+2), nullptr, nullptr, msg_b + l * 128, nullptr, nullptr,
            nullptr, nullptr, src, dst, p1, p2, agg, E, 128);
        mmagemm<2,2,true,false><<<gN, 256, SMEM_BYTES>>>(hhi, hlo, agg,
            whi + WUPD_OFF + (size_t)l * 32768, wlo + WUPD_OFF + (size_t)l * 32768,
            nullptr, nullptr, upd_b + l * 128, h, nullptr, hhi, hlo,
            nullptr, nullptr, nullptr, nullptr, agg, N, 256);
    }

    // ---- decoder ----
    mmagemm<0,0,true,false><<<gN, 256, SMEM_BYTES>>>(hhi, hlo, nullptr, WH(2), WL(2),
        nullptr, nullptr, dec_b1, f1, nullptr, nullptr, nullptr,
        nullptr, nullptr, nullptr, nullptr, nullptr, N, 128);
    dec2_kernel<<<(N + 63) / 64, 128>>>(f1, dec_W2, dec_b2, dec_W3, dec_b3,
                                        bc_disp, bc_rot, face_mask, (float*)d_out, N);
}

// round 8
// speedup vs baseline: 3.0086x; 1.3072x over previous
#include <cuda_runtime.h>
#include <cuda_bf16.h>
#include <cstdint>

// ===========================================================================
// PIGNN forward — mma.sync bf16 hi/lo split GEMMs.
// Persistent CTAs, continuous 3-stage cp.async pipeline across tiles,
// register-direct epilogues (no C smem staging).
//   msg_in @ mW == h[src]@mW1 + h[dst]@mW2 + e@mW3
// ===========================================================================

#define NN_MAX 100000
#define NE_MAX 600000

__device__ float g_h   [(size_t)NN_MAX * 128];
__device__ float g_agg [(size_t)NN_MAX * 128];
__device__ float g_f1  [(size_t)NN_MAX * 128];
__device__ float g_p1  [(size_t)NN_MAX * 128];
__device__ float g_p2  [(size_t)NN_MAX * 128];
__device__ __nv_bfloat16 g_hhi[(size_t)NN_MAX * 128];
__device__ __nv_bfloat16 g_hlo[(size_t)NN_MAX * 128];
__device__ __nv_bfloat16 g_ehi[(size_t)NE_MAX * 128];
__device__ __nv_bfloat16 g_elo[(size_t)NE_MAX * 128];
__device__ __nv_bfloat16 g_thi[(size_t)NE_MAX * 128];
__device__ __nv_bfloat16 g_tlo[(size_t)NE_MAX * 128];
#define W128_CNT 21
#define WUPD_OFF (W128_CNT * 16384)
#define WTOT (WUPD_OFF + 6 * 32768)
__device__ __nv_bfloat16 g_whi[WTOT];
__device__ __nv_bfloat16 g_wlo[WTOT];
__device__ float g_zbias[128];   // zero-initialized, never written

// ---------------------------------------------------------------------------
__device__ __forceinline__ uint32_t smem_to_u32(const void* p) {
    uint32_t a;
    asm("{ .reg .u64 t; cvta.to.shared.u64 t, %1; cvt.u32.u64 %0, t; }" : "=r"(a) : "l"(p));
    return a;
}
__device__ __forceinline__ void ldmx4(uint32_t& r0, uint32_t& r1, uint32_t& r2, uint32_t& r3,
                                      uint32_t addr) {
    asm volatile("ldmatrix.sync.aligned.m8n8.x4.shared.b16 {%0,%1,%2,%3}, [%4];"
                 : "=r"(r0), "=r"(r1), "=r"(r2), "=r"(r3) : "r"(addr));
}
__device__ __forceinline__ void mma_bf16(float& c0, float& c1, float& c2, float& c3,
                                         uint32_t a0, uint32_t a1, uint32_t a2, uint32_t a3,
                                         uint32_t b0, uint32_t b1) {
    asm volatile("mma.sync.aligned.m16n8k16.row.col.f32.bf16.bf16.f32 "
                 "{%0,%1,%2,%3}, {%4,%5,%6,%7}, {%8,%9}, {%0,%1,%2,%3};"
                 : "+f"(c0), "+f"(c1), "+f"(c2), "+f"(c3)
                 : "r"(a0), "r"(a1), "r"(a2), "r"(a3), "r"(b0), "r"(b1));
}
__device__ __forceinline__ void cpa16(uint32_t saddr, const void* g) {
    asm volatile("cp.async.cg.shared.global [%0], [%1], 16;" :: "r"(saddr), "l"(g));
}
#define CP_COMMIT() asm volatile("cp.async.commit_group;" ::: "memory")
#define CP_WAIT2()  asm volatile("cp.async.wait_group 2;" ::: "memory")
#define CP_WAIT1()  asm volatile("cp.async.wait_group 1;" ::: "memory")
#define CP_WAIT0()  asm volatile("cp.async.wait_group 0;" ::: "memory")
__device__ __forceinline__ void red_add_v2(float* addr, float a, float b) {
    asm volatile("red.global.add.v2.f32 [%0], {%1,%2};"
                 :: "l"(addr), "f"(a), "f"(b) : "memory");
}
__device__ __forceinline__ uint32_t pack_bf2(float a, float b) {
    __nv_bfloat162 v = __floats2bfloat162_rn(a, b);
    return *reinterpret_cast<uint32_t*>(&v);
}
// split two floats into hi (bf16x2) and lo (bf16x2) packed words
__device__ __forceinline__ void split2(float a, float b, uint32_t& hp, uint32_t& lp) {
    __nv_bfloat16 ha = __float2bfloat16(a), hb = __float2bfloat16(b);
    float la = a - __bfloat162float(ha), lb = b - __bfloat162float(hb);
    __nv_bfloat162 hh = __nv_bfloat162(ha, hb);
    hp = *reinterpret_cast<uint32_t*>(&hh);
    lp = pack_bf2(la, lb);
}
__device__ __forceinline__ void split4(const float4 v, uint32_t& h01, uint32_t& h23,
                                       uint32_t& l01, uint32_t& l23) {
    split2(v.x, v.y, h01, l01);
    split2(v.z, v.w, h23, l23);
}

// ---------------------------------------------------------------------------
// SMEM: 3 stages x (AHI 8K | ALO 8K | BHI 8K | BLO 8K) = 96KB.
// Slab = 128 rows x 32 bf16 (64B rows), 16B chunks 0..3, swizzled.
#define OFF_AHI 0
#define OFF_ALO 8192
#define OFF_BHI 16384
#define OFF_BLO 24576
#define STAGE 32768
#define SMEM_BYTES (3 * STAGE)
#define SWZ(row, chunk) ((uint32_t)(row) * 64 + ((uint32_t)((chunk) ^ (((row) >> 1) & 3)) << 4))

// ---------------------------------------------------------------------------
// GEMM: tile 128x128, K-slab 32, 3-pass bf16 split, 256 thr (8 warps 4x2),
// persistent tiles with continuous 3-stage cp.async pipeline.
// MODE: 0 A = pre-split bf16 (lda=128) | 2 upd: slabs 0-3 pre-split h, 4-7 fp32 agg
// EPI : 0 store fp32 (RELU opt) | 1 store split | 2 h+=relu + split + zero agg
//       3 msg RED scatter | 4 store fp32 + split
// DUAL: tiles >= ntiles/2 use Bhi2/Blo2 -> Cout2.
template<int MODE, int EPI, bool RELU, bool DUAL>
__global__ __launch_bounds__(256, 2)
void mmagemm(const __nv_bfloat16* __restrict__ Ahi, const __nv_bfloat16* __restrict__ Alo,
             const float* __restrict__ Af2,
             const __nv_bfloat16* __restrict__ Bhi_, const __nv_bfloat16* __restrict__ Blo_,
             const __nv_bfloat16* __restrict__ Bhi2, const __nv_bfloat16* __restrict__ Blo2,
             const float* __restrict__ bias,
             float* __restrict__ Cout_, float* __restrict__ Cout2,
             __nv_bfloat16* __restrict__ OutHi, __nv_bfloat16* __restrict__ OutLo,
             const int* __restrict__ src, const int* __restrict__ dst,
             const float* __restrict__ P1, const float* __restrict__ P2,
             float* __restrict__ AGGZ,
             int M, int K, int ntiles)
{
    extern __shared__ char smem[];
    const uint32_t sb = smem_to_u32(smem);
    const int t = threadIdx.x;
    const int lane = t & 31;
    const int wid = t >> 5;
    const int wm = wid & 3;
    const int wn = wid >> 2;
    const int gridSz = gridDim.x;
    const int bid = blockIdx.x;
    const int nslabs = K >> 5;
    const int halfT = DUAL ? (ntiles >> 1) : ntiles;

    // per-lane bias pairs in registers
    const int c2 = (lane & 3) * 2;
    float2 bw[8];
#pragma unroll
    for (int jn = 0; jn < 8; ++jn)
        bw[jn] = *reinterpret_cast<const float2*>(&bias[wn * 64 + jn * 8 + c2]);

    const int ntl = (bid < ntiles) ? ((ntiles - 1 - bid) / gridSz + 1) : 0;
    const int L = ntl * nslabs;

    float acc[2][8][4];
#pragma unroll
    for (int i = 0; i < 2; ++i)
#pragma unroll
        for (int j = 0; j < 8; ++j)
#pragma unroll
            for (int r = 0; r < 4; ++r) acc[i][j][r] = 0.f;

    auto issue_fill = [&](int l) {
        const int tl = l / nslabs;
        const int s = l - tl * nslabs;
        const int tt = bid + tl * gridSz;
        const __nv_bfloat16* bhi = Bhi_;
        const __nv_bfloat16* blo = Blo_;
        int mt = tt;
        if (DUAL && tt >= halfT) { mt -= halfT; bhi = Bhi2; blo = Blo2; }
        const int m0f = mt * 128;
        const int kb = s << 5;
        const uint32_t stOff = (uint32_t)(l % 3) * STAGE;
        const uint32_t buf = sb + stOff;
        if (MODE == 2 && s >= 4) {
            // A from fp32 agg: synchronous register split
#pragma unroll
            for (int i = 0; i < 2; ++i) {
                int id = t + i * 256;
                int row = id >> 2;
                int c = id & 3;
                int m = m0f + row;
                int mc = m < M ? m : M - 1;
                const float* g = &Af2[(size_t)mc * 128 + (kb - 128) + c * 8];
                float4 v0 = *reinterpret_cast<const float4*>(g);
                float4 v1 = *reinterpret_cast<const float4*>(g + 4);
                uint32_t h01, h23, l01, l23, h45, h67, l45, l67;
                split4(v0, h01, h23, l01, l23);
                split4(v1, h45, h67, l45, l67);
                uint32_t off = SWZ(row, c);
                *reinterpret_cast<uint4*>(smem + stOff + OFF_AHI + off) =
                    make_uint4(h01, h23, h45, h67);
                *reinterpret_cast<uint4*>(smem + stOff + OFF_ALO + off) =
                    make_uint4(l01, l23, l45, l67);
            }
#pragma unroll
            for (int i = 0; i < 2; ++i) {
                int id = t + i * 256;
                int row = id >> 2;
                int c = id & 3;
                uint32_t off = SWZ(row, c);
                cpa16(buf + OFF_BHI + off, bhi + (size_t)row * K + kb + c * 8);
                cpa16(buf + OFF_BLO + off, blo + (size_t)row * K + kb + c * 8);
            }
        } else {
#pragma unroll
            for (int i = 0; i < 2; ++i) {
                int id = t + i * 256;
                int row = id >> 2;
                int c = id & 3;
                int m = m0f + row;
                int mc = m < M ? m : M - 1;
                uint32_t off = SWZ(row, c);
                cpa16(buf + OFF_AHI + off, Ahi + (size_t)mc * 128 + kb + c * 8);
                cpa16(buf + OFF_ALO + off, Alo + (size_t)mc * 128 + kb + c * 8);
                cpa16(buf + OFF_BHI + off, bhi + (size_t)row * K + kb + c * 8);
                cpa16(buf + OFF_BLO + off, blo + (size_t)row * K + kb + c * 8);
            }
        }
        CP_COMMIT();
    };

    if (L > 0) { issue_fill(0); if (L > 1) issue_fill(1); }

    int tl_cur = 0;
    int s_in = 0;
    for (int l = 0; l < L; ++l) {
        __syncthreads();          // prior stage readers + epilogues done
        if (l + 2 < L) { issue_fill(l + 2); CP_WAIT2(); }
        else if (l + 1 < L) { CP_WAIT1(); }
        else { CP_WAIT0(); }
        __syncthreads();          // fills (incl. MODE2 sync writes) visible
        const uint32_t buf = sb + (uint32_t)(l % 3) * STAGE;
#pragma unroll
        for (int ks = 0; ks < 2; ++ks) {
            uint32_t ahi[2][4], alo[2][4];
            uint32_t ca = ks * 2 + (lane >> 4);
            uint32_t arow = wm * 32 + (lane & 15);
#pragma unroll
            for (int i = 0; i < 2; ++i) {
                uint32_t r = arow + i * 16;
                uint32_t off = SWZ(r, ca);
                ldmx4(ahi[i][0], ahi[i][1], ahi[i][2], ahi[i][3], buf + OFF_AHI + off);
                ldmx4(alo[i][0], alo[i][1], alo[i][2], alo[i][3], buf + OFF_ALO + off);
            }
            uint32_t nr = wn * 64 + (lane & 7) + (lane >> 4) * 8;
            uint32_t cbk = ks * 2 + ((lane >> 3) & 1);
#pragma unroll
            for (int j2 = 0; j2 < 4; ++j2) {
                uint32_t r = nr + j2 * 16;
                uint32_t off = SWZ(r, cbk);
                uint32_t bh[4], bl[4];
                ldmx4(bh[0], bh[1], bh[2], bh[3], buf + OFF_BHI + off);
                ldmx4(bl[0], bl[1], bl[2], bl[3], buf + OFF_BLO + off);
#pragma unroll
                for (int i = 0; i < 2; ++i) {
#pragma unroll
                    for (int jj = 0; jj < 2; ++jj) {
                        float* c = acc[i][j2 * 2 + jj];
                        mma_bf16(c[0], c[1], c[2], c[3],
                                 ahi[i][0], ahi[i][1], ahi[i][2], ahi[i][3],
                                 bh[jj * 2], bh[jj * 2 + 1]);
                        mma_bf16(c[0], c[1], c[2], c[3],
                                 alo[i][0], alo[i][1], alo[i][2], alo[i][3],
                                 bh[jj * 2], bh[jj * 2 + 1]);
                        mma_bf16(c[0], c[1], c[2], c[3],
                                 ahi[i][0], ahi[i][1], ahi[i][2], ahi[i][3],
                                 bl[jj * 2], bl[jj * 2 + 1]);
                    }
                }
            }
        }

        if (++s_in == nslabs) {
            s_in = 0;
            // ---- register-direct epilogue for tile tl_cur (overlaps inflight fills)
            const int tt = bid + tl_cur * gridSz;
            ++tl_cur;
            float* co = Cout_;
            int mt = tt;
            if (DUAL && tt >= halfT) { mt -= halfT; co = Cout2; }
            const int m0 = mt * 128;
#pragma unroll
            for (int i = 0; i < 2; ++i) {
                const int ra = m0 + wm * 32 + i * 16 + (lane >> 2);
                const int rb = ra + 8;
                const bool va = ra < M, vb = rb < M;
                int sA = 0, dA = 0, sB = 0, dB = 0;
                if (EPI == 3) {
                    if (va) { sA = __ldg(&src[ra]); dA = __ldg(&dst[ra]); }
                    if (vb) { sB = __ldg(&src[rb]); dB = __ldg(&dst[rb]); }
                }
#pragma unroll
                for (int jn = 0; jn < 8; ++jn) {
                    float* c = acc[i][jn];
                    const int col = wn * 64 + jn * 8 + c2;
                    float v0 = c[0] + bw[jn].x, v1 = c[1] + bw[jn].y;
                    float v2 = c[2] + bw[jn].x, v3 = c[3] + bw[jn].y;
                    c[0] = c[1] = c[2] = c[3] = 0.f;
                    if (EPI == 0 || EPI == 4) {
                        if (RELU) { v0 = fmaxf(v0, 0.f); v1 = fmaxf(v1, 0.f);
                                    v2 = fmaxf(v2, 0.f); v3 = fmaxf(v3, 0.f); }
                        if (va) *reinterpret_cast<float2*>(&co[(size_t)ra * 128 + col]) =
                            make_float2(v0, v1);
                        if (vb) *reinterpret_cast<float2*>(&co[(size_t)rb * 128 + col]) =
                            make_float2(v2, v3);
                        if (EPI == 4) {
                            uint32_t hp, lp;
                            if (va) {
                                split2(v0, v1, hp, lp);
                                *reinterpret_cast<uint32_t*>(OutHi + (size_t)ra * 128 + col) = hp;
                                *reinterpret_cast<uint32_t*>(OutLo + (size_t)ra * 128 + col) = lp;
                            }
                            if (vb) {
                                split2(v2, v3, hp, lp);
                                *reinterpret_cast<uint32_t*>(OutHi + (size_t)rb * 128 + col) = hp;
                                *reinterpret_cast<uint32_t*>(OutLo + (size_t)rb * 128 + col) = lp;
                            }
                        }
                    } else if (EPI == 1) {
                        uint32_t hp, lp;
                        if (va) {
                            split2(v0, v1, hp, lp);
                            *reinterpret_cast<uint32_t*>(OutHi + (size_t)ra * 128 + col) = hp;
                            *reinterpret_cast<uint32_t*>(OutLo + (size_t)ra * 128 + col) = lp;
                        }
                        if (vb) {
                            split2(v2, v3, hp, lp);
                            *reinterpret_cast<uint32_t*>(OutHi + (size_t)rb * 128 + col) = hp;
                            *reinterpret_cast<uint32_t*>(OutLo + (size_t)rb * 128 + col) = lp;
                        }
                    } else if (EPI == 2) {
                        uint32_t hp, lp;
                        if (va) {
                            float2 o = *reinterpret_cast<float2*>(&co[(size_t)ra * 128 + col]);
                            o.x += fmaxf(v0, 0.f); o.y += fmaxf(v1, 0.f);
                            *reinterpret_cast<float2*>(&co[(size_t)ra * 128 + col]) = o;
                            split2(o.x, o.y, hp, lp);
                            *reinterpret_cast<uint32_t*>(OutHi + (size_t)ra * 128 + col) = hp;
                            *reinterpret_cast<uint32_t*>(OutLo + (size_t)ra * 128 + col) = lp;
                            *reinterpret_cast<float2*>(&AGGZ[(size_t)ra * 128 + col]) =
                                make_float2(0.f, 0.f);
                        }
                        if (vb) {
                            float2 o = *reinterpret_cast<float2*>(&co[(size_t)rb * 128 + col]);
                            o.x += fmaxf(v2, 0.f); o.y += fmaxf(v3, 0.f);
                            *reinterpret_cast<float2*>(&co[(size_t)rb * 128 + col]) = o;
                            split2(o.x, o.y, hp, lp);
                            *reinterpret_cast<uint32_t*>(OutHi + (size_t)rb * 128 + col) = hp;
                            *reinterpret_cast<uint32_t*>(OutLo + (size_t)rb * 128 + col) = lp;
                            *reinterpret_cast<float2*>(&AGGZ[(size_t)rb * 128 + col]) =
                                make_float2(0.f, 0.f);
                        }
                    } else {  // EPI 3
                        if (va) {
                            float2 a1 = __ldg(reinterpret_cast<const float2*>(
                                                  &P1[(size_t)sA * 128 + col]));
                            float2 a2 = __ldg(reinterpret_cast<const float2*>(
                                                  &P2[(size_t)dA * 128 + col]));
                            float x0 = fmaxf(v0 + a1.x + a2.x, 0.f);
                            float x1 = fmaxf(v1 + a1.y + a2.y, 0.f);
                            red_add_v2(&AGGZ[(size_t)dA * 128 + col], x0, x1);
                        }
                        if (vb) {
                            float2 a1 = __ldg(reinterpret_cast<const float2*>(
                                                  &P1[(size_t)sB * 128 + col]));
                            float2 a2 = __ldg(reinterpret_cast<const float2*>(
                                                  &P2[(size_t)dB * 128 + col]));
                            float x2 = fmaxf(v2 + a1.x + a2.x, 0.f);
                            float x3 = fmaxf(v3 + a1.y + a2.y, 0.f);
                            red_add_v2(&AGGZ[(size_t)dB * 128 + col], x2, x3);
                        }
                    }
                }
            }
        }
    }
}

// ---------------------------------------------------------------------------
struct PtrTab { const float* p[W128_CNT]; };

__global__ void prep_w128(PtrTab tab, __nv_bfloat16* __restrict__ hi, __nv_bfloat16* __restrict__ lo) {
    int mat = blockIdx.y;
    int i = blockIdx.x * 256 + threadIdx.x;
    if (i >= 16384) return;
    int n = i >> 7, k = i & 127;
    float w = tab.p[mat][k * 128 + n];
    __nv_bfloat16 h = __float2bfloat16(w);
    hi[(size_t)mat * 16384 + i] = h;
    lo[(size_t)mat * 16384 + i] = __float2bfloat16(w - __bfloat162float(h));
}
__global__ void prep_w256(const float* __restrict__ W, __nv_bfloat16* __restrict__ hi,
                          __nv_bfloat16* __restrict__ lo) {
    int mat = blockIdx.y;
    int i = blockIdx.x * 256 + threadIdx.x;
    if (i >= 32768) return;
    int n = i >> 8, k = i & 255;
    float w = W[(size_t)mat * 256 * 128 + k * 128 + n];
    __nv_bfloat16 h = __float2bfloat16(w);
    hi[(size_t)(WUPD_OFF + mat * 32768) + i] = h;
    lo[(size_t)(WUPD_OFF + mat * 32768) + i] = __float2bfloat16(w - __bfloat162float(h));
}

__global__ void zero_kernel(float* __restrict__ p, int n4) {
    int i = blockIdx.x * blockDim.x + threadIdx.x;
    if (i < n4) reinterpret_cast<float4*>(p)[i] = make_float4(0.f, 0.f, 0.f, 0.f);
}

// batched tiny-K first linear + relu, writes pre-split bf16 hi/lo
__global__ void mlp1_kernel(const float* __restrict__ X, const float* __restrict__ W,
                            const float* __restrict__ b,
                            __nv_bfloat16* __restrict__ outHi, __nv_bfloat16* __restrict__ outLo,
                            int K, int M)
{
    __shared__ float Ws[10 * 128];
    __shared__ float Xs[32 * 10];
    __shared__ float bs[128];
    int t = threadIdx.x;  // 128
    for (int i = t; i < K * 128; i += 128) Ws[i] = W[i];
    bs[t] = b[t];
    int r0 = blockIdx.x * 32;
    int nrow = min(32, M - r0);
    for (int i = t; i < nrow * K; i += 128) Xs[i] = X[(size_t)r0 * K + i];
    __syncthreads();
    for (int r = 0; r < nrow; ++r) {
        float acc = bs[t];
        for (int k = 0; k < K; ++k) acc += Xs[r * K + k] * Ws[k * 128 + t];
        acc = fmaxf(acc, 0.f);
        __nv_bfloat16 hv = __float2bfloat16(acc);
        outHi[(size_t)(r0 + r) * 128 + t] = hv;
        outLo[(size_t)(r0 + r) * 128 + t] = __float2bfloat16(acc - __bfloat162float(hv));
    }
}

// fused decoder tail
__global__ void dec2_kernel(const float* __restrict__ f1, const float* __restrict__ W2,
                            const float* __restrict__ b2, const float* __restrict__ W3,
                            const float* __restrict__ b3, const float* __restrict__ bc_disp,
                            const float* __restrict__ bc_rot, const float* __restrict__ face_mask,
                            float* __restrict__ out, int N)
{
    __shared__ float W2s[128 * 64];
    __shared__ float W3s[64 * 15];
    __shared__ float b2s[64], b3s[16];
    __shared__ float f1s[2][128];
    __shared__ float f2s[2][64];

    int t = threadIdx.x;
    for (int i = t; i < 128 * 64; i += 128) W2s[i] = W2[i];
    for (int i = t; i < 64 * 15;  i += 128) W3s[i] = W3[i];
    if (t < 64) b2s[t] = b2[t];
    if (t < 15) b3s[t] = b3[t];
    __syncthreads();

    int base = blockIdx.x * 64;
    for (int it = 0; it < 32; ++it) {
        int n0 = base + it * 2;
#pragma unroll
        for (int r = 0; r < 2; ++r) {
            int n = n0 + r;
            f1s[r][t] = (n < N) ? f1[(size_t)n * 128 + t] : 0.f;
        }
        __syncthreads();
        {
            int rn = t >> 6, j = t & 63;
            float acc = b2s[j];
#pragma unroll 8
            for (int k = 0; k < 128; ++k) acc += f1s[rn][k] * W2s[k * 64 + j];
            f2s[rn][j] = fmaxf(acc, 0.f);
        }
        __syncthreads();
        if (t < 30) {
            int rr = t / 15, c = t % 15;
            int n = n0 + rr;
            if (n < N) {
                float acc = b3s[c];
#pragma unroll 8
                for (int k = 0; k < 64; ++k) acc += f2s[rr][k] * W3s[k * 15 + c];
                float mask;
                if (c < 2)       mask = 1.f - bc_disp[n];
                else if (c == 2) mask = 1.f - bc_rot[n];
                else             mask = face_mask[(size_t)n * 4 + (c - 3) / 3];
                out[(size_t)n * 15 + c] = acc * mask;
            }
        }
        __syncthreads();
    }
}

// ---------------------------------------------------------------------------
extern "C" void kernel_launch(void* const* d_in, const int* in_sizes, int n_in,
                              void* d_out, int out_size)
{
    const float* x         = (const float*)d_in[0];
    const float* edge_attr = (const float*)d_in[1];
    const int*   edge_idx  = (const int*)  d_in[2];
    const float* bc_disp   = (const float*)d_in[3];
    const float* bc_rot    = (const float*)d_in[4];
    const float* face_mask = (const float*)d_in[5];
    const float* enc_n_W1  = (const float*)d_in[6];
    const float* enc_n_b1  = (const float*)d_in[7];
    const float* enc_n_W2  = (const float*)d_in[8];
    const float* enc_n_b2  = (const float*)d_in[9];
    const float* enc_e_W1  = (const float*)d_in[10];
    const float* enc_e_b1  = (const float*)d_in[11];
    const float* enc_e_W2  = (const float*)d_in[12];
    const float* enc_e_b2  = (const float*)d_in[13];
    const float* msg_W     = (const float*)d_in[14];
    const float* msg_b     = (const float*)d_in[15];
    const float* upd_W     = (const float*)d_in[16];
    const float* upd_b     = (const float*)d_in[17];
    const float* dec_W1    = (const float*)d_in[18];
    const float* dec_b1    = (const float*)d_in[19];
    const float* dec_W2    = (const float*)d_in[20];
    const float* dec_b2    = (const float*)d_in[21];
    const float* dec_W3    = (const float*)d_in[22];
    const float* dec_b3    = (const float*)d_in[23];

    const int N = in_sizes[0] / 9;
    const int E = in_sizes[1] / 10;
    const int* src = edge_idx;
    const int* dst = edge_idx + E;

    float *h, *agg, *f1, *p1, *p2, *zb;
    __nv_bfloat16 *hhi, *hlo, *ehi, *elo, *thi, *tlo, *whi, *wlo;
    cudaGetSymbolAddress((void**)&h,   g_h);
    cudaGetSymbolAddress((void**)&agg, g_agg);
    cudaGetSymbolAddress((void**)&f1,  g_f1);
    cudaGetSymbolAddress((void**)&p1,  g_p1);
    cudaGetSymbolAddress((void**)&p2,  g_p2);
    cudaGetSymbolAddress((void**)&zb,  g_zbias);
    cudaGetSymbolAddress((void**)&hhi, g_hhi);
    cudaGetSymbolAddress((void**)&hlo, g_hlo);
    cudaGetSymbolAddress((void**)&ehi, g_ehi);
    cudaGetSymbolAddress((void**)&elo, g_elo);
    cudaGetSymbolAddress((void**)&thi, g_thi);
    cudaGetSymbolAddress((void**)&tlo, g_tlo);
    cudaGetSymbolAddress((void**)&whi, g_whi);
    cudaGetSymbolAddress((void**)&wlo, g_wlo);

    cudaFuncSetAttribute((const void*)mmagemm<0,4,false,false>, cudaFuncAttributeMaxDynamicSharedMemorySize, SMEM_BYTES);
    cudaFuncSetAttribute((const void*)mmagemm<0,1,false,false>, cudaFuncAttributeMaxDynamicSharedMemorySize, SMEM_BYTES);
    cudaFuncSetAttribute((const void*)mmagemm<0,0,false,true>,  cudaFuncAttributeMaxDynamicSharedMemorySize, SMEM_BYTES);
    cudaFuncSetAttribute((const void*)mmagemm<0,0,true,false>,  cudaFuncAttributeMaxDynamicSharedMemorySize, SMEM_BYTES);
    cudaFuncSetAttribute((const void*)mmagemm<0,3,true,false>,  cudaFuncAttributeMaxDynamicSharedMemorySize, SMEM_BYTES);
    cudaFuncSetAttribute((const void*)mmagemm<2,2,true,false>,  cudaFuncAttributeMaxDynamicSharedMemorySize, SMEM_BYTES);

    // ---- weight prep ----
    PtrTab tab;
    tab.p[0] = enc_n_W2;
    tab.p[1] = enc_e_W2;
    tab.p[2] = dec_W1;
    for (int l = 0; l < 6; ++l)
        for (int j = 0; j < 3; ++j)
            tab.p[3 + l * 3 + j] = msg_W + (size_t)l * 384 * 128 + (size_t)j * 128 * 128;
    prep_w128<<<dim3(64, W128_CNT), 256>>>(tab, whi, wlo);
    prep_w256<<<dim3(128, 6), 256>>>(upd_W, whi, wlo);

    const int gN = (N + 127) / 128;
    const int gE = (E + 127) / 128;
    const int PG = 296;   // persistent grid: 2 CTAs x 148 SMs
    auto grid_for = [&](int nt) { return nt < PG ? nt : PG; };
    auto WH = [&](int j) { return whi + (size_t)j * 16384; };
    auto WL = [&](int j) { return wlo + (size_t)j * 16384; };

    // ---- encoders ----
    mlp1_kernel<<<(N + 31) / 32, 128>>>(x, enc_n_W1, enc_n_b1, thi, tlo, 9, N);
    mmagemm<0,4,false,false><<<grid_for(gN), 256, SMEM_BYTES>>>(thi, tlo, nullptr, WH(0), WL(0),
        nullptr, nullptr, enc_n_b2, h, nullptr, hhi, hlo,
        nullptr, nullptr, nullptr, nullptr, nullptr, N, 128, gN);
    mlp1_kernel<<<(E + 31) / 32, 128>>>(edge_attr, enc_e_W1, enc_e_b1, thi, tlo, 10, E);
    mmagemm<0,1,false,false><<<grid_for(gE), 256, SMEM_BYTES>>>(thi, tlo, nullptr, WH(1), WL(1),
        nullptr, nullptr, enc_e_b2, nullptr, nullptr, ehi, elo,
        nullptr, nullptr, nullptr, nullptr, nullptr, E, 128, gE);

    zero_kernel<<<(N * 128 / 4 + 255) / 256, 256>>>(agg, N * 128 / 4);

    // ---- message-passing layers ----
    for (int l = 0; l < 6; ++l) {
        int j = 3 + l * 3;
        mmagemm<0,0,false,true><<<grid_for(2 * gN), 256, SMEM_BYTES>>>(hhi, hlo, nullptr,
            WH(j), WL(j), WH(j+1), WL(j+1), zb, p1, p2, nullptr, nullptr,
            nullptr, nullptr, nullptr, nullptr, nullptr, N, 128, 2 * gN);
        mmagemm<0,3,true,false><<<grid_for(gE), 256, SMEM_BYTES>>>(ehi, elo, nullptr,
            WH(j+2), WL(j+2), nullptr, nullptr, msg_b + l * 128, nullptr, nullptr,
            nullptr, nullptr, src, dst, p1, p2, agg, E, 128, gE);
        mmagemm<2,2,true,false><<<grid_for(gN), 256, SMEM_BYTES>>>(hhi, hlo, agg,
            whi + WUPD_OFF + (size_t)l * 32768, wlo + WUPD_OFF + (size_t)l * 32768,
            nullptr, nullptr, upd_b + l * 128, h, nullptr, hhi, hlo,
            nullptr, nullptr, nullptr, nullptr, agg, N, 256, gN);
    }

    // ---- decoder ----
    mmagemm<0,0,true,false><<<grid_for(gN), 256, SMEM_BYTES>>>(hhi, hlo, nullptr, WH(2), WL(2),
        nullptr, nullptr, dec_b1, f1, nullptr, nullptr, nullptr,
        nullptr, nullptr, nullptr, nullptr, nullptr, N, 128, gN);
    dec2_kernel<<<(N + 63) / 64, 128>>>(f1, dec_W2, dec_b2, dec_W3, dec_b3,
                                        bc_disp, bc_rot, face_mask, (float*)d_out, N);
}

// round 9
// speedup vs baseline: 3.0517x; 1.0143x over previous
#include <cuda_runtime.h>
#include <cuda_bf16.h>
#include <cstdint>

// ===========================================================================
// PIGNN forward — mma.sync bf16 hi/lo split GEMMs, persistent-B in smem.
// All GEMMs are K=128 with one resident B (hi+lo, 64KB) per CTA; A streams
// through a 2-stage cp.async pipeline. Persistent CTAs, register epilogues.
//   msg_in @ mW == h[src]@mW1 + h[dst]@mW2 + e@mW3
//   upd == relu(h@uW1 + agg@uW2 + ub); agg pre-split by splitagg kernel.
// ===========================================================================

#define NN_MAX 100000
#define NE_MAX 600000

__device__ float g_h   [(size_t)NN_MAX * 128];
__device__ float g_agg [(size_t)NN_MAX * 128];
__device__ float g_f1  [(size_t)NN_MAX * 128];   // U1 during layers, f1 in decoder
__device__ float g_p1  [(size_t)NN_MAX * 128];
__device__ float g_p2  [(size_t)NN_MAX * 128];
__device__ __nv_bfloat16 g_hhi[(size_t)NN_MAX * 128];
__device__ __nv_bfloat16 g_hlo[(size_t)NN_MAX * 128];
__device__ __nv_bfloat16 g_ehi[(size_t)NE_MAX * 128];
__device__ __nv_bfloat16 g_elo[(size_t)NE_MAX * 128];
__device__ __nv_bfloat16 g_thi[(size_t)NE_MAX * 128];   // mlp1 out / agg-split
__device__ __nv_bfloat16 g_tlo[(size_t)NE_MAX * 128];
#define W128_CNT 21
#define WUPD_OFF (W128_CNT * 16384)
#define WTOT (WUPD_OFF + 6 * 32768)
__device__ __nv_bfloat16 g_whi[WTOT];
__device__ __nv_bfloat16 g_wlo[WTOT];
__device__ float g_zbias[128];   // zero-initialized, never written

// ---------------------------------------------------------------------------
__device__ __forceinline__ uint32_t smem_to_u32(const void* p) {
    uint32_t a;
    asm("{ .reg .u64 t; cvta.to.shared.u64 t, %1; cvt.u32.u64 %0, t; }" : "=r"(a) : "l"(p));
    return a;
}
__device__ __forceinline__ void ldmx4(uint32_t& r0, uint32_t& r1, uint32_t& r2, uint32_t& r3,
                                      uint32_t addr) {
    asm volatile("ldmatrix.sync.aligned.m8n8.x4.shared.b16 {%0,%1,%2,%3}, [%4];"
                 : "=r"(r0), "=r"(r1), "=r"(r2), "=r"(r3) : "r"(addr));
}
__device__ __forceinline__ void mma_bf16(float& c0, float& c1, float& c2, float& c3,
                                         uint32_t a0, uint32_t a1, uint32_t a2, uint32_t a3,
                                         uint32_t b0, uint32_t b1) {
    asm volatile("mma.sync.aligned.m16n8k16.row.col.f32.bf16.bf16.f32 "
                 "{%0,%1,%2,%3}, {%4,%5,%6,%7}, {%8,%9}, {%0,%1,%2,%3};"
                 : "+f"(c0), "+f"(c1), "+f"(c2), "+f"(c3)
                 : "r"(a0), "r"(a1), "r"(a2), "r"(a3), "r"(b0), "r"(b1));
}
__device__ __forceinline__ void cpa16(uint32_t saddr, const void* g) {
    asm volatile("cp.async.cg.shared.global [%0], [%1], 16;" :: "r"(saddr), "l"(g));
}
#define CP_COMMIT() asm volatile("cp.async.commit_group;" ::: "memory")
#define CP_WAIT1()  asm volatile("cp.async.wait_group 1;" ::: "memory")
#define CP_WAIT0()  asm volatile("cp.async.wait_group 0;" ::: "memory")
__device__ __forceinline__ void red_add_v2(float* addr, float a, float b) {
    asm volatile("red.global.add.v2.f32 [%0], {%1,%2};"
                 :: "l"(addr), "f"(a), "f"(b) : "memory");
}
__device__ __forceinline__ uint32_t pack_bf2(float a, float b) {
    __nv_bfloat162 v = __floats2bfloat162_rn(a, b);
    return *reinterpret_cast<uint32_t*>(&v);
}
__device__ __forceinline__ void split2(float a, float b, uint32_t& hp, uint32_t& lp) {
    __nv_bfloat16 ha = __float2bfloat16(a), hb = __float2bfloat16(b);
    float la = a - __bfloat162float(ha), lb = b - __bfloat162float(hb);
    __nv_bfloat162 hh = __nv_bfloat162(ha, hb);
    hp = *reinterpret_cast<uint32_t*>(&hh);
    lp = pack_bf2(la, lb);
}
__device__ __forceinline__ void split4(const float4 v, uint32_t& h01, uint32_t& h23,
                                       uint32_t& l01, uint32_t& l23) {
    split2(v.x, v.y, h01, l01);
    split2(v.z, v.w, h23, l23);
}

// ---------------------------------------------------------------------------
// SMEM: persistent B (hi 32K @0, lo 32K @32768; 4 slabs x 8K each) +
// 2 A stages @65536 (each: AHI 8K + ALO 8K = 16K). Total 96KB -> 2 CTAs/SM.
#define OFF_BLOP 32768
#define OFF_AST  65536
#define SMEM_BYTES (OFF_AST + 2 * 16384)
#define SWZ(row, chunk) ((uint32_t)(row) * 64 + ((uint32_t)((chunk) ^ (((row) >> 1) & 3)) << 4))

struct Seg { const __nv_bfloat16* bhi; const __nv_bfloat16* blo;
             const float* bias; float* cout; int ldb; };
struct Segs { Seg s[3]; };

// ---------------------------------------------------------------------------
// GEMM: tile 128x128, K=128 (4 slabs of 32), 3-pass bf16 split, 256 thr,
// persistent B in smem, persistent CTAs, 2-stage A pipeline.
// EPI: 0 store fp32 (RELU opt) | 1 store split | 3 msg RED | 4 fp32+split
//      5 upd2: o=relu(U1+acc+b); cout+=o; split cout; (agg already zeroed)
// NSEG: static CTA partition over up to 3 (B, bias, cout) segments.
template<int EPI, bool RELU, int NSEG>
__global__ __launch_bounds__(256, 2)
void gk(Segs segs,
        const __nv_bfloat16* __restrict__ Ahi, const __nv_bfloat16* __restrict__ Alo,
        __nv_bfloat16* __restrict__ OutHi, __nv_bfloat16* __restrict__ OutLo,
        const int* __restrict__ src, const int* __restrict__ dst,
        const float* __restrict__ P1, const float* __restrict__ P2,
        float* __restrict__ AGGZ, const float* __restrict__ U1,
        int M, int ntiles)
{
    extern __shared__ char smem[];
    const uint32_t sb = smem_to_u32(smem);
    const int t = threadIdx.x;
    const int lane = t & 31;
    const int wid = t >> 5;
    const int wm = wid & 3;
    const int wn = wid >> 2;

    const int seg  = (NSEG == 1) ? 0 : (blockIdx.x % NSEG);
    const int nbSeg = gridDim.x / NSEG;
    const int bidS = (NSEG == 1) ? blockIdx.x : (blockIdx.x / NSEG);
    const Seg sg = segs.s[seg];

    const int ntl = (bidS < ntiles) ? ((ntiles - 1 - bidS) / nbSeg + 1) : 0;
    const int L = ntl * 4;
    if (L == 0) return;

    const int c2 = (lane & 3) * 2;
    float2 bw[8];
#pragma unroll
    for (int jn = 0; jn < 8; ++jn)
        bw[jn] = *reinterpret_cast<const float2*>(&sg.bias[wn * 64 + jn * 8 + c2]);

    // ---- persistent B load (4 slabs, hi+lo) ----
#pragma unroll
    for (int i = 0; i < 8; ++i) {
        int id = t + i * 256;            // 0..2047
        int slab = id >> 9;
        int row = (id >> 2) & 127;
        int c = id & 3;
        uint32_t off = (uint32_t)slab * 8192 + SWZ(row, c);
        size_t gix = (size_t)row * sg.ldb + slab * 32 + c * 8;
        cpa16(sb + off, sg.bhi + gix);
        cpa16(sb + OFF_BLOP + off, sg.blo + gix);
    }
    CP_COMMIT();

    auto fillA = [&](int l) {
        int tl = l >> 2;
        int s = l & 3;
        int m0f = (bidS + tl * nbSeg) * 128;
        int kb = s << 5;
        uint32_t buf = sb + OFF_AST + (uint32_t)(l & 1) * 16384;
#pragma unroll
        for (int i = 0; i < 2; ++i) {
            int id = t + i * 256;
            int row = id >> 2;
            int c = id & 3;
            int m = m0f + row;
            int mc = m < M ? m : M - 1;
            uint32_t off = SWZ(row, c);
            cpa16(buf + off, Ahi + (size_t)mc * 128 + kb + c * 8);
            cpa16(buf + 8192 + off, Alo + (size_t)mc * 128 + kb + c * 8);
        }
        CP_COMMIT();
    };

    fillA(0);

    float acc[2][8][4];
#pragma unroll
    for (int i = 0; i < 2; ++i)
#pragma unroll
        for (int j = 0; j < 8; ++j)
#pragma unroll
            for (int r = 0; r < 4; ++r) acc[i][j][r] = 0.f;

    int tl_cur = 0;
    for (int l = 0; l < L; ++l) {
        __syncthreads();                       // prior readers of next stage done
        if (l + 1 < L) { fillA(l + 1); CP_WAIT1(); }
        else CP_WAIT0();
        __syncthreads();                       // fills visible
        const uint32_t bufA = sb + OFF_AST + (uint32_t)(l & 1) * 16384;
        const uint32_t bufB = sb + (uint32_t)(l & 3) * 8192;
#pragma unroll
        for (int ks = 0; ks < 2; ++ks) {
            uint32_t ahi[2][4], alo[2][4];
            uint32_t ca = ks * 2 + (lane >> 4);
            uint32_t arow = wm * 32 + (lane & 15);
#pragma unroll
            for (int i = 0; i < 2; ++i) {
                uint32_t r = arow + i * 16;
                uint32_t off = SWZ(r, ca);
                ldmx4(ahi[i][0], ahi[i][1], ahi[i][2], ahi[i][3], bufA + off);
                ldmx4(alo[i][0], alo[i][1], alo[i][2], alo[i][3], bufA + 8192 + off);
            }
            uint32_t nr = wn * 64 + (lane & 7) + (lane >> 4) * 8;
            uint32_t cbk = ks * 2 + ((lane >> 3) & 1);
#pragma unroll
            for (int j2 = 0; j2 < 4; ++j2) {
                uint32_t r = nr + j2 * 16;
                uint32_t off = SWZ(r, cbk);
                uint32_t bh[4], bl[4];
                ldmx4(bh[0], bh[1], bh[2], bh[3], bufB + off);
                ldmx4(bl[0], bl[1], bl[2], bl[3], bufB + OFF_BLOP + off);
#pragma unroll
                for (int i = 0; i < 2; ++i) {
#pragma unroll
                    for (int jj = 0; jj < 2; ++jj) {
                        float* c = acc[i][j2 * 2 + jj];
                        mma_bf16(c[0], c[1], c[2], c[3],
                                 ahi[i][0], ahi[i][1], ahi[i][2], ahi[i][3],
                                 bh[jj * 2], bh[jj * 2 + 1]);
                        mma_bf16(c[0], c[1], c[2], c[3],
                                 alo[i][0], alo[i][1], alo[i][2], alo[i][3],
                                 bh[jj * 2], bh[jj * 2 + 1]);
                        mma_bf16(c[0], c[1], c[2], c[3],
                                 ahi[i][0], ahi[i][1], ahi[i][2], ahi[i][3],
                                 bl[jj * 2], bl[jj * 2 + 1]);
                    }
                }
            }
        }

        if ((l & 3) == 3) {
            // ---- register-direct epilogue for tile tl_cur ----
            const int m0 = (bidS + tl_cur * nbSeg) * 128;
            ++tl_cur;
            float* co = sg.cout;
#pragma unroll
            for (int i = 0; i < 2; ++i) {
                const int ra = m0 + wm * 32 + i * 16 + (lane >> 2);
                const int rb = ra + 8;
                const bool va = ra < M, vb = rb < M;
                int sA = 0, dA = 0, sB = 0, dB = 0;
                if (EPI == 3) {
                    if (va) { sA = __ldg(&src[ra]); dA = __ldg(&dst[ra]); }
                    if (vb) { sB = __ldg(&src[rb]); dB = __ldg(&dst[rb]); }
                }
#pragma unroll
                for (int jn = 0; jn < 8; ++jn) {
                    float* c = acc[i][jn];
                    const int col = wn * 64 + jn * 8 + c2;
                    float v0 = c[0] + bw[jn].x, v1 = c[1] + bw[jn].y;
                    float v2 = c[2] + bw[jn].x, v3 = c[3] + bw[jn].y;
                    c[0] = c[1] = c[2] = c[3] = 0.f;
                    if (EPI == 0 || EPI == 4) {
                        if (RELU) { v0 = fmaxf(v0, 0.f); v1 = fmaxf(v1, 0.f);
                                    v2 = fmaxf(v2, 0.f); v3 = fmaxf(v3, 0.f); }
                        if (va) *reinterpret_cast<float2*>(&co[(size_t)ra * 128 + col]) =
                            make_float2(v0, v1);
                        if (vb) *reinterpret_cast<float2*>(&co[(size_t)rb * 128 + col]) =
                            make_float2(v2, v3);
                        if (EPI == 4) {
                            uint32_t hp, lp;
                            if (va) {
                                split2(v0, v1, hp, lp);
                                *reinterpret_cast<uint32_t*>(OutHi + (size_t)ra * 128 + col) = hp;
                                *reinterpret_cast<uint32_t*>(OutLo + (size_t)ra * 128 + col) = lp;
                            }
                            if (vb) {
                                split2(v2, v3, hp, lp);
                                *reinterpret_cast<uint32_t*>(OutHi + (size_t)rb * 128 + col) = hp;
                                *reinterpret_cast<uint32_t*>(OutLo + (size_t)rb * 128 + col) = lp;
                            }
                        }
                    } else if (EPI == 1) {
                        uint32_t hp, lp;
                        if (va) {
                            split2(v0, v1, hp, lp);
                            *reinterpret_cast<uint32_t*>(OutHi + (size_t)ra * 128 + col) = hp;
                            *reinterpret_cast<uint32_t*>(OutLo + (size_t)ra * 128 + col) = lp;
                        }
                        if (vb) {
                            split2(v2, v3, hp, lp);
                            *reinterpret_cast<uint32_t*>(OutHi + (size_t)rb * 128 + col) = hp;
                            *reinterpret_cast<uint32_t*>(OutLo + (size_t)rb * 128 + col) = lp;
                        }
                    } else if (EPI == 5) {
                        uint32_t hp, lp;
                        if (va) {
                            float2 u = __ldg(reinterpret_cast<const float2*>(
                                                 &U1[(size_t)ra * 128 + col]));
                            float2 o = *reinterpret_cast<float2*>(&co[(size_t)ra * 128 + col]);
                            o.x += fmaxf(v0 + u.x, 0.f);
                            o.y += fmaxf(v1 + u.y, 0.f);
                            *reinterpret_cast<float2*>(&co[(size_t)ra * 128 + col]) = o;
                            split2(o.x, o.y, hp, lp);
                            *reinterpret_cast<uint32_t*>(OutHi + (size_t)ra * 128 + col) = hp;
                            *reinterpret_cast<uint32_t*>(OutLo + (size_t)ra * 128 + col) = lp;
                        }
                        if (vb) {
                            float2 u = __ldg(reinterpret_cast<const float2*>(
                                                 &U1[(size_t)rb * 128 + col]));
                            float2 o = *reinterpret_cast<float2*>(&co[(size_t)rb * 128 + col]);
                            o.x += fmaxf(v2 + u.x, 0.f);
                            o.y += fmaxf(v3 + u.y, 0.f);
                            *reinterpret_cast<float2*>(&co[(size_t)rb * 128 + col]) = o;
                            split2(o.x, o.y, hp, lp);
                            *reinterpret_cast<uint32_t*>(OutHi + (size_t)rb * 128 + col) = hp;
                            *reinterpret_cast<uint32_t*>(OutLo + (size_t)rb * 128 + col) = lp;
                        }
                    } else {  // EPI 3
                        if (va) {
                            float2 a1 = __ldg(reinterpret_cast<const float2*>(
                                                  &P1[(size_t)sA * 128 + col]));
                            float2 a2 = __ldg(reinterpret_cast<const float2*>(
                                                  &P2[(size_t)dA * 128 + col]));
                            float x0 = fmaxf(v0 + a1.x + a2.x, 0.f);
                            float x1 = fmaxf(v1 + a1.y + a2.y, 0.f);
                            red_add_v2(&AGGZ[(size_t)dA * 128 + col], x0, x1);
                        }
                        if (vb) {
                            float2 a1 = __ldg(reinterpret_cast<const float2*>(
                                                  &P1[(size_t)sB * 128 + col]));
                            float2 a2 = __ldg(reinterpret_cast<const float2*>(
                                                  &P2[(size_t)dB * 128 + col]));
                            float x2 = fmaxf(v2 + a1.x + a2.x, 0.f);
                            float x3 = fmaxf(v3 + a1.y + a2.y, 0.f);
                            red_add_v2(&AGGZ[(size_t)dB * 128 + col], x2, x3);
                        }
                    }
                }
            }
        }
    }
}

// ---------------------------------------------------------------------------
// split agg (fp32) -> bf16 hi/lo, and zero agg for the next layer
__global__ void splitagg(float* __restrict__ agg, __nv_bfloat16* __restrict__ hi,
                         __nv_bfloat16* __restrict__ lo, int n4) {
    int i = blockIdx.x * blockDim.x + threadIdx.x;
    if (i >= n4) return;
    float4 v = reinterpret_cast<float4*>(agg)[i];
    uint32_t h01, h23, l01, l23;
    split4(v, h01, h23, l01, l23);
    reinterpret_cast<uint2*>(hi)[i] = make_uint2(h01, h23);
    reinterpret_cast<uint2*>(lo)[i] = make_uint2(l01, l23);
    reinterpret_cast<float4*>(agg)[i] = make_float4(0.f, 0.f, 0.f, 0.f);
}

// ---------------------------------------------------------------------------
struct PtrTab { const float* p[W128_CNT]; };

__global__ void prep_w128(PtrTab tab, __nv_bfloat16* __restrict__ hi, __nv_bfloat16* __restrict__ lo) {
    int mat = blockIdx.y;
    int i = blockIdx.x * 256 + threadIdx.x;
    if (i >= 16384) return;
    int n = i >> 7, k = i & 127;
    float w = tab.p[mat][k * 128 + n];
    __nv_bfloat16 h = __float2bfloat16(w);
    hi[(size_t)mat * 16384 + i] = h;
    lo[(size_t)mat * 16384 + i] = __float2bfloat16(w - __bfloat162float(h));
}
__global__ void prep_w256(const float* __restrict__ W, __nv_bfloat16* __restrict__ hi,
                          __nv_bfloat16* __restrict__ lo) {
    int mat = blockIdx.y;
    int i = blockIdx.x * 256 + threadIdx.x;
    if (i >= 32768) return;
    int n = i >> 8, k = i & 255;
    float w = W[(size_t)mat * 256 * 128 + k * 128 + n];
    __nv_bfloat16 h = __float2bfloat16(w);
    hi[(size_t)(WUPD_OFF + mat * 32768) + i] = h;
    lo[(size_t)(WUPD_OFF + mat * 32768) + i] = __float2bfloat16(w - __bfloat162float(h));
}

__global__ void zero_kernel(float* __restrict__ p, int n4) {
    int i = blockIdx.x * blockDim.x + threadIdx.x;
    if (i < n4) reinterpret_cast<float4*>(p)[i] = make_float4(0.f, 0.f, 0.f, 0.f);
}

// batched tiny-K first linear + relu, writes pre-split bf16 hi/lo
__global__ void mlp1_kernel(const float* __restrict__ X, const float* __restrict__ W,
                            const float* __restrict__ b,
                            __nv_bfloat16* __restrict__ outHi, __nv_bfloat16* __restrict__ outLo,
                            int K, int M)
{
    __shared__ float Ws[10 * 128];
    __shared__ float Xs[32 * 10];
    __shared__ float bs[128];
    int t = threadIdx.x;  // 128
    for (int i = t; i < K * 128; i += 128) Ws[i] = W[i];
    bs[t] = b[t];
    int r0 = blockIdx.x * 32;
    int nrow = min(32, M - r0);
    for (int i = t; i < nrow * K; i += 128) Xs[i] = X[(size_t)r0 * K + i];
    __syncthreads();
    for (int r = 0; r < nrow; ++r) {
        float acc = bs[t];
        for (int k = 0; k < K; ++k) acc += Xs[r * K + k] * Ws[k * 128 + t];
        acc = fmaxf(acc, 0.f);
        __nv_bfloat16 hv = __float2bfloat16(acc);
        outHi[(size_t)(r0 + r) * 128 + t] = hv;
        outLo[(size_t)(r0 + r) * 128 + t] = __float2bfloat16(acc - __bfloat162float(hv));
    }
}

// fused decoder tail
__global__ void dec2_kernel(const float* __restrict__ f1, const float* __restrict__ W2,
                            const float* __restrict__ b2, const float* __restrict__ W3,
                            const float* __restrict__ b3, const float* __restrict__ bc_disp,
                            const float* __restrict__ bc_rot, const float* __restrict__ face_mask,
                            float* __restrict__ out, int N)
{
    __shared__ float W2s[128 * 64];
    __shared__ float W3s[64 * 15];
    __shared__ float b2s[64], b3s[16];
    __shared__ float f1s[2][128];
    __shared__ float f2s[2][64];

    int t = threadIdx.x;
    for (int i = t; i < 128 * 64; i += 128) W2s[i] = W2[i];
    for (int i = t; i < 64 * 15;  i += 128) W3s[i] = W3[i];
    if (t < 64) b2s[t] = b2[t];
    if (t < 15) b3s[t] = b3[t];
    __syncthreads();

    int base = blockIdx.x * 64;
    for (int it = 0; it < 32; ++it) {
        int n0 = base + it * 2;
#pragma unroll
        for (int r = 0; r < 2; ++r) {
            int n = n0 + r;
            f1s[r][t] = (n < N) ? f1[(size_t)n * 128 + t] : 0.f;
        }
        __syncthreads();
        {
            int rn = t >> 6, j = t & 63;
            float acc = b2s[j];
#pragma unroll 8
            for (int k = 0; k < 128; ++k) acc += f1s[rn][k] * W2s[k * 64 + j];
            f2s[rn][j] = fmaxf(acc, 0.f);
        }
        __syncthreads();
        if (t < 30) {
            int rr = t / 15, c = t % 15;
            int n = n0 + rr;
            if (n < N) {
                float acc = b3s[c];
#pragma unroll 8
                for (int k = 0; k < 64; ++k) acc += f2s[rr][k] * W3s[k * 15 + c];
                float mask;
                if (c < 2)       mask = 1.f - bc_disp[n];
                else if (c == 2) mask = 1.f - bc_rot[n];
                else             mask = face_mask[(size_t)n * 4 + (c - 3) / 3];
                out[(size_t)n * 15 + c] = acc * mask;
            }
        }
        __syncthreads();
    }
}

// ---------------------------------------------------------------------------
extern "C" void kernel_launch(void* const* d_in, const int* in_sizes, int n_in,
                              void* d_out, int out_size)
{
    const float* x         = (const float*)d_in[0];
    const float* edge_attr = (const float*)d_in[1];
    const int*   edge_idx  = (const int*)  d_in[2];
    const float* bc_disp   = (const float*)d_in[3];
    const float* bc_rot    = (const float*)d_in[4];
    const float* face_mask = (const float*)d_in[5];
    const float* enc_n_W1  = (const float*)d_in[6];
    const float* enc_n_b1  = (const float*)d_in[7];
    const float* enc_n_W2  = (const float*)d_in[8];
    const float* enc_n_b2  = (const float*)d_in[9];
    const float* enc_e_W1  = (const float*)d_in[10];
    const float* enc_e_b1  = (const float*)d_in[11];
    const float* enc_e_W2  = (const float*)d_in[12];
    const float* enc_e_b2  = (const float*)d_in[13];
    const float* msg_W     = (const float*)d_in[14];
    const float* msg_b     = (const float*)d_in[15];
    const float* upd_W     = (const float*)d_in[16];
    const float* upd_b     = (const float*)d_in[17];
    const float* dec_W1    = (const float*)d_in[18];
    const float* dec_b1    = (const float*)d_in[19];
    const float* dec_W2    = (const float*)d_in[20];
    const float* dec_b2    = (const float*)d_in[21];
    const float* dec_W3    = (const float*)d_in[22];
    const float* dec_b3    = (const float*)d_in[23];

    const int N = in_sizes[0] / 9;
    const int E = in_sizes[1] / 10;
    const int* src = edge_idx;
    const int* dst = edge_idx + E;

    float *h, *agg, *f1, *p1, *p2, *zb;
    __nv_bfloat16 *hhi, *hlo, *ehi, *elo, *thi, *tlo, *whi, *wlo;
    cudaGetSymbolAddress((void**)&h,   g_h);
    cudaGetSymbolAddress((void**)&agg, g_agg);
    cudaGetSymbolAddress((void**)&f1,  g_f1);
    cudaGetSymbolAddress((void**)&p1,  g_p1);
    cudaGetSymbolAddress((void**)&p2,  g_p2);
    cudaGetSymbolAddress((void**)&zb,  g_zbias);
    cudaGetSymbolAddress((void**)&hhi, g_hhi);
    cudaGetSymbolAddress((void**)&hlo, g_hlo);
    cudaGetSymbolAddress((void**)&ehi, g_ehi);
    cudaGetSymbolAddress((void**)&elo, g_elo);
    cudaGetSymbolAddress((void**)&thi, g_thi);
    cudaGetSymbolAddress((void**)&tlo, g_tlo);
    cudaGetSymbolAddress((void**)&whi, g_whi);
    cudaGetSymbolAddress((void**)&wlo, g_wlo);

    cudaFuncSetAttribute((const void*)gk<0,false,3>, cudaFuncAttributeMaxDynamicSharedMemorySize, SMEM_BYTES);
    cudaFuncSetAttribute((const void*)gk<3,true,1>,  cudaFuncAttributeMaxDynamicSharedMemorySize, SMEM_BYTES);
    cudaFuncSetAttribute((const void*)gk<5,true,1>,  cudaFuncAttributeMaxDynamicSharedMemorySize, SMEM_BYTES);
    cudaFuncSetAttribute((const void*)gk<4,false,1>, cudaFuncAttributeMaxDynamicSharedMemorySize, SMEM_BYTES);
    cudaFuncSetAttribute((const void*)gk<1,false,1>, cudaFuncAttributeMaxDynamicSharedMemorySize, SMEM_BYTES);
    cudaFuncSetAttribute((const void*)gk<0,true,1>,  cudaFuncAttributeMaxDynamicSharedMemorySize, SMEM_BYTES);

    // ---- weight prep ----
    PtrTab tab;
    tab.p[0] = enc_n_W2;
    tab.p[1] = enc_e_W2;
    tab.p[2] = dec_W1;
    for (int l = 0; l < 6; ++l)
        for (int j = 0; j < 3; ++j)
            tab.p[3 + l * 3 + j] = msg_W + (size_t)l * 384 * 128 + (size_t)j * 128 * 128;
    prep_w128<<<dim3(64, W128_CNT), 256>>>(tab, whi, wlo);
    prep_w256<<<dim3(128, 6), 256>>>(upd_W, whi, wlo);

    const int gN = (N + 127) / 128;
    const int gE = (E + 127) / 128;
    auto WH = [&](int j) { return whi + (size_t)j * 16384; };
    auto WL = [&](int j) { return wlo + (size_t)j * 16384; };
    auto mkseg = [](const __nv_bfloat16* bh, const __nv_bfloat16* bl,
                    const float* bi, float* co, int ldb) {
        Seg s; s.bhi = bh; s.blo = bl; s.bias = bi; s.cout = co; s.ldb = ldb; return s;
    };

    const int PG1 = 296;                   // NSEG=1 grid
    const int PG3 = 294;                   // NSEG=3 grid (divisible by 3)
    auto g1 = [&](int nt) { return nt < PG1 ? nt : PG1; };

    // ---- encoders ----
    mlp1_kernel<<<(N + 31) / 32, 128>>>(x, enc_n_W1, enc_n_b1, thi, tlo, 9, N);
    {
        Segs sg; sg.s[0] = mkseg(WH(0), WL(0), enc_n_b2, h, 128);
        gk<4,false,1><<<g1(gN), 256, SMEM_BYTES>>>(sg, thi, tlo, hhi, hlo,
            nullptr, nullptr, nullptr, nullptr, nullptr, nullptr, N, gN);
    }
    mlp1_kernel<<<(E + 31) / 32, 128>>>(edge_attr, enc_e_W1, enc_e_b1, thi, tlo, 10, E);
    {
        Segs sg; sg.s[0] = mkseg(WH(1), WL(1), enc_e_b2, nullptr, 128);
        gk<1,false,1><<<g1(gE), 256, SMEM_BYTES>>>(sg, thi, tlo, ehi, elo,
            nullptr, nullptr, nullptr, nullptr, nullptr, nullptr, E, gE);
    }

    zero_kernel<<<(N * 128 / 4 + 255) / 256, 256>>>(agg, N * 128 / 4);

    // ---- message-passing layers ----
    for (int l = 0; l < 6; ++l) {
        int j = 3 + l * 3;
        const __nv_bfloat16* uh = whi + WUPD_OFF + (size_t)l * 32768;
        const __nv_bfloat16* ul = wlo + WUPD_OFF + (size_t)l * 32768;
        {   // P1 = h@mW1, P2 = h@mW2, U1 = h@uW1 (3 segments)
            Segs sg;
            sg.s[0] = mkseg(WH(j),   WL(j),   zb, p1, 128);
            sg.s[1] = mkseg(WH(j+1), WL(j+1), zb, p2, 128);
            sg.s[2] = mkseg(uh, ul, zb, f1, 256);
            int grid = (3 * gN < PG3) ? 3 * gN : PG3;
            gk<0,false,3><<<grid, 256, SMEM_BYTES>>>(sg, hhi, hlo, nullptr, nullptr,
                nullptr, nullptr, nullptr, nullptr, nullptr, nullptr, N, gN);
        }
        {   // msg: acc=e@mW3; epi relu(acc+b+P1[src]+P2[dst]) RED->agg[dst]
            Segs sg; sg.s[0] = mkseg(WH(j+2), WL(j+2), msg_b + l * 128, nullptr, 128);
            gk<3,true,1><<<g1(gE), 256, SMEM_BYTES>>>(sg, ehi, elo, nullptr, nullptr,
                src, dst, p1, p2, agg, nullptr, E, gE);
        }
        // agg -> bf16 hi/lo (thi/tlo), zero agg
        splitagg<<<(N * 32 + 255) / 256, 256>>>(agg, thi, tlo, N * 32);
        {   // upd2: o = relu(U1 + agg@uW2 + ub); h += o; split h
            Segs sg; sg.s[0] = mkseg(uh + 128, ul + 128, upd_b + l * 128, h, 256);
            gk<5,true,1><<<g1(gN), 256, SMEM_BYTES>>>(sg, thi, tlo, hhi, hlo,
                nullptr, nullptr, nullptr, nullptr, nullptr, f1, N, gN);
        }
    }

    // ---- decoder ----
    {
        Segs sg; sg.s[0] = mkseg(WH(2), WL(2), dec_b1, f1, 128);
        gk<0,true,1><<<g1(gN), 256, SMEM_BYTES>>>(sg, hhi, hlo, nullptr, nullptr,
            nullptr, nullptr, nullptr, nullptr, nullptr, nullptr, N, gN);
    }
    dec2_kernel<<<(N + 63) / 64, 128>>>(f1, dec_W2, dec_b2, dec_W3, dec_b3,
                                        bc_disp, bc_rot, face_mask, (float*)d_out, N);
}